// round 6
// baseline (speedup 1.0000x reference)
#include <cuda_runtime.h>
#include <cuda_fp16.h>
#include <cstdint>

#define N_NODES 50000
#define N_EDGES 800000
#define E_TOT   (N_EDGES + N_NODES)
#define IN_DIM  256
#define OUT_DIM 256   // N_HEADS * HEAD_DIM
#define NEG_SLOPE 0.2f

// ---------------- scratch (static device globals; no runtime allocation) ---
__device__ __align__(16) __half g_xph[(size_t)N_NODES * OUT_DIM]; // projected features, fp16 [N,256]
__device__ __align__(16) float g_Wa[IN_DIM * 8];                  // folded attn weights [256][8] (src 0..3, dst 4..7)
__device__ __align__(16) float g_asrc[N_NODES * 4];               // per-node src logits [N,4]
__device__ __align__(16) float g_adst[N_NODES * 4];               // per-node dst logits [N,4]
__device__ __align__(16) float g_csr_ee[(size_t)E_TOT * 4];       // exp(logit), CSR order [E+N,4]
__device__ int g_csr_src[E_TOT];                                  // src node id, CSR order
__device__ int g_deg[N_NODES];                                    // in-degree histogram
__device__ int g_off[N_NODES];                                    // CSR row start
__device__ int g_cur[N_NODES];                                    // scatter cursor -> row end
__device__ int g_is64;                                            // edge_index dtype flag

// ---------------- helpers --------------------------------------------------
__device__ __forceinline__ uint32_t f2tf32(float f) {
    uint32_t r;
    asm("cvt.rna.tf32.f32 %0, %1;" : "=r"(r) : "f"(f));
    return r;
}

__device__ __forceinline__ void load_edge(const void* ei, int i, int& s, int& d) {
    if (g_is64) {
        const long long* p = (const long long*)ei;
        s = (int)p[i];
        d = (int)p[N_EDGES + i];
    } else {
        const int* p = (const int*)ei;
        s = p[i];
        d = p[N_EDGES + i];
    }
}

// ---------------- K-1: dtype detection -------------------------------------
__global__ void detect_dtype_kernel(const int* __restrict__ ei32) {
    if (threadIdx.x == 0 && blockIdx.x == 0) {
        int any = 0;
        for (int k = 0; k < 128; k++) any |= ei32[2 * k + 1];
        g_is64 = (any == 0) ? 1 : 0;
    }
}

// ---------------- K0: zero degree histogram --------------------------------
__global__ void zero_deg_kernel() {
    int i = blockIdx.x * blockDim.x + threadIdx.x;
    if (i < N_NODES) g_deg[i] = 0;
}

// ---------------- K0b: fold att vectors into W -----------------------------
// Wa[k][h]   = sum_c W[k][h*64+c] * att_src[h][c]   (h = 0..3)
// Wa[k][h+4] = sum_c W[k][h*64+c] * att_dst[h][c]
__global__ __launch_bounds__(256) void fold_att_kernel(
    const float* __restrict__ Wm,
    const float* __restrict__ att_src, const float* __restrict__ att_dst)
{
    int idx = blockIdx.x * blockDim.x + threadIdx.x;   // 0..2047
    if (idx >= IN_DIM * 8) return;
    int k = idx >> 3;
    int o = idx & 7;
    int h = o & 3;
    const float* att = (o < 4) ? att_src : att_dst;
    const float* wrow = Wm + (size_t)k * OUT_DIM + h * 64;
    float s = 0.f;
#pragma unroll 16
    for (int c = 0; c < 64; c++) s += wrow[c] * att[h * 64 + c];
    g_Wa[k * 8 + o] = s;
}

// ---------------- K1: GEMM xp = x @ W  (tf32 mma.sync, fp16 output) --------
#define GBM 128
#define GBN 128
#define GBK 32
#define A_LD (GBK + 4)
#define B_LD (GBN + 4)

__global__ __launch_bounds__(256) void gemm_tf32_kernel(
    const float* __restrict__ X, const float* __restrict__ Wm)
{
    __shared__ uint32_t As[GBM][A_LD];
    __shared__ uint32_t Bs[GBK][B_LD];

    const int tid  = threadIdx.x;
    const int wid  = tid >> 5;
    const int lane = tid & 31;
    const int m0 = blockIdx.x * GBM;
    const int n0 = blockIdx.y * GBN;
    const int wm = (wid & 1) * 64;
    const int wn = (wid >> 1) * 32;
    const int gID = lane >> 2;
    const int tig = lane & 3;

    float c[4][4][4];
#pragma unroll
    for (int i = 0; i < 4; i++)
#pragma unroll
        for (int j = 0; j < 4; j++)
#pragma unroll
            for (int r = 0; r < 4; r++) c[i][j][r] = 0.f;

    for (int k0 = 0; k0 < IN_DIM; k0 += GBK) {
#pragma unroll
        for (int l = 0; l < 4; l++) {
            int idx = tid + l * 256;
            int row = idx >> 3;
            int c4  = idx & 7;
            int gm  = m0 + row;
            float4 v = make_float4(0.f, 0.f, 0.f, 0.f);
            if (gm < N_NODES)
                v = *reinterpret_cast<const float4*>(X + (size_t)gm * IN_DIM + k0 + c4 * 4);
            As[row][c4 * 4 + 0] = f2tf32(v.x);
            As[row][c4 * 4 + 1] = f2tf32(v.y);
            As[row][c4 * 4 + 2] = f2tf32(v.z);
            As[row][c4 * 4 + 3] = f2tf32(v.w);
        }
#pragma unroll
        for (int l = 0; l < 4; l++) {
            int idx = tid + l * 256;
            int kr = idx >> 5;
            int c4 = idx & 31;
            float4 v = *reinterpret_cast<const float4*>(
                Wm + (size_t)(k0 + kr) * OUT_DIM + n0 + c4 * 4);
            Bs[kr][c4 * 4 + 0] = f2tf32(v.x);
            Bs[kr][c4 * 4 + 1] = f2tf32(v.y);
            Bs[kr][c4 * 4 + 2] = f2tf32(v.z);
            Bs[kr][c4 * 4 + 3] = f2tf32(v.w);
        }
        __syncthreads();

#pragma unroll
        for (int ks = 0; ks < 4; ks++) {
            const int kb = ks * 8;
            uint32_t a[4][4], b[4][2];
#pragma unroll
            for (int mt = 0; mt < 4; mt++) {
                int rb = wm + mt * 16;
                a[mt][0] = As[rb + gID    ][kb + tig    ];
                a[mt][1] = As[rb + gID + 8][kb + tig    ];
                a[mt][2] = As[rb + gID    ][kb + tig + 4];
                a[mt][3] = As[rb + gID + 8][kb + tig + 4];
            }
#pragma unroll
            for (int nt = 0; nt < 4; nt++) {
                int col = wn + nt * 8 + gID;
                b[nt][0] = Bs[kb + tig    ][col];
                b[nt][1] = Bs[kb + tig + 4][col];
            }
#pragma unroll
            for (int mt = 0; mt < 4; mt++)
#pragma unroll
                for (int nt = 0; nt < 4; nt++) {
                    asm volatile(
                        "mma.sync.aligned.m16n8k8.row.col.f32.tf32.tf32.f32 "
                        "{%0,%1,%2,%3}, {%4,%5,%6,%7}, {%8,%9}, {%0,%1,%2,%3};"
                        : "+f"(c[mt][nt][0]), "+f"(c[mt][nt][1]),
                          "+f"(c[mt][nt][2]), "+f"(c[mt][nt][3])
                        : "r"(a[mt][0]), "r"(a[mt][1]), "r"(a[mt][2]), "r"(a[mt][3]),
                          "r"(b[nt][0]), "r"(b[nt][1]));
                }
        }
        __syncthreads();
    }

#pragma unroll
    for (int mt = 0; mt < 4; mt++) {
        int r0 = m0 + wm + mt * 16 + gID;
#pragma unroll
        for (int nt = 0; nt < 4; nt++) {
            int col = n0 + wn + nt * 8 + 2 * tig;
            if (r0 < N_NODES) {
                __half2 v01 = __floats2half2_rn(c[mt][nt][0], c[mt][nt][1]);
                *reinterpret_cast<__half2*>(g_xph + (size_t)r0 * OUT_DIM + col) = v01;
            }
            if (r0 + 8 < N_NODES) {
                __half2 v23 = __floats2half2_rn(c[mt][nt][2], c[mt][nt][3]);
                *reinterpret_cast<__half2*>(g_xph + (size_t)(r0 + 8) * OUT_DIM + col) = v23;
            }
        }
    }
}

// ---------------- K2: attention logits from x @ Wa (skinny GEMV) -----------
// warp per node: lane holds x[n, lane*8 .. lane*8+7]; 8 outputs reduced by shfl
__global__ __launch_bounds__(256) void attn_gemv_kernel(const float* __restrict__ X)
{
    __shared__ float sWa[IN_DIM * 8];
    // load Wa into smem: 2048 floats, 8 per thread
    {
        int t = threadIdx.x;
        float4* dst = reinterpret_cast<float4*>(sWa);
        const float4* src = reinterpret_cast<const float4*>(g_Wa);
#pragma unroll
        for (int l = 0; l < 2; l++) dst[t + l * 256] = src[t + l * 256];
    }
    __syncthreads();

    int warp = (blockIdx.x * blockDim.x + threadIdx.x) >> 5;
    if (warp >= N_NODES) return;
    int lane = threadIdx.x & 31;

    const float4* xr = reinterpret_cast<const float4*>(X + (size_t)warp * IN_DIM + lane * 8);
    float4 xv0 = xr[0], xv1 = xr[1];
    float xv[8] = {xv0.x, xv0.y, xv0.z, xv0.w, xv1.x, xv1.y, xv1.z, xv1.w};

    float acc[8];
#pragma unroll
    for (int o = 0; o < 8; o++) acc[o] = 0.f;
#pragma unroll
    for (int i = 0; i < 8; i++) {
        const float* wr = sWa + (lane * 8 + i) * 8;
#pragma unroll
        for (int o = 0; o < 8; o++) acc[o] += xv[i] * wr[o];
    }
#pragma unroll
    for (int off = 16; off > 0; off >>= 1)
#pragma unroll
        for (int o = 0; o < 8; o++)
            acc[o] += __shfl_down_sync(0xffffffffu, acc[o], off);

    if (lane == 0) {
        *reinterpret_cast<float4*>(g_asrc + warp * 4) =
            make_float4(acc[0], acc[1], acc[2], acc[3]);
        *reinterpret_cast<float4*>(g_adst + warp * 4) =
            make_float4(acc[4], acc[5], acc[6], acc[7]);
    }
}

// ---------------- K3a: in-degree histogram ---------------------------------
__global__ __launch_bounds__(256) void hist_kernel(const void* __restrict__ ei)
{
    int i = blockIdx.x * blockDim.x + threadIdx.x;
    if (i >= E_TOT) return;
    int s, d;
    if (i < N_EDGES) load_edge(ei, i, s, d);
    else             d = i - N_EDGES;
    atomicAdd(&g_deg[d], 1);
}

// ---------------- K3b: single-block exclusive scan -> offsets + cursors ----
#define SCAN_T 1024
__global__ __launch_bounds__(SCAN_T) void scan_kernel()
{
    __shared__ int sums[SCAN_T];
    const int t = threadIdx.x;
    const int CH = (N_NODES + SCAN_T - 1) / SCAN_T;   // 49
    const int lo = t * CH;
    const int hi = (lo + CH < N_NODES) ? lo + CH : N_NODES;

    int s = 0;
    for (int i = lo; i < hi; i++) s += g_deg[i];
    sums[t] = s;
    __syncthreads();

    for (int off = 1; off < SCAN_T; off <<= 1) {
        int v = (t >= off) ? sums[t - off] : 0;
        __syncthreads();
        sums[t] += v;
        __syncthreads();
    }

    int run = (t == 0) ? 0 : sums[t - 1];
    for (int i = lo; i < hi; i++) {
        int dg = g_deg[i];
        g_off[i] = run;
        g_cur[i] = run;
        run += dg;
    }
}

// ---------------- K3c: scatter edges into CSR order + compute exp(logit) ---
__global__ __launch_bounds__(256) void scatter_kernel(const void* __restrict__ ei)
{
    int i = blockIdx.x * blockDim.x + threadIdx.x;
    if (i >= E_TOT) return;
    int s, d;
    if (i < N_EDGES) load_edge(ei, i, s, d);
    else             s = d = i - N_EDGES;   // self-loop

    float4 as = *reinterpret_cast<const float4*>(g_asrc + s * 4);
    float4 ad = *reinterpret_cast<const float4*>(g_adst + d * 4);
    float e0 = as.x + ad.x, e1 = as.y + ad.y, e2 = as.z + ad.z, e3 = as.w + ad.w;
    e0 = (e0 > 0.f) ? e0 : NEG_SLOPE * e0;
    e1 = (e1 > 0.f) ? e1 : NEG_SLOPE * e1;
    e2 = (e2 > 0.f) ? e2 : NEG_SLOPE * e2;
    e3 = (e3 > 0.f) ? e3 : NEG_SLOPE * e3;
    float4 ee = make_float4(__expf(e0), __expf(e1), __expf(e2), __expf(e3));

    int pos = atomicAdd(&g_cur[d], 1);
    g_csr_src[pos] = s;
    *reinterpret_cast<float4*>(g_csr_ee + (size_t)pos * 4) = ee;
}

// ---------------- K4: CSR aggregate, unroll-4 MLP, fused softmax + ReLU ----
__global__ __launch_bounds__(256) void aggregate_csr_kernel(float* __restrict__ out)
{
    int d = (blockIdx.x * blockDim.x + threadIdx.x) >> 5;
    if (d >= N_NODES) return;
    int lane = threadIdx.x & 31;
    int h = lane >> 3;
    int beg = g_off[d];
    int end = g_cur[d];

    float a0 = 0.f, a1 = 0.f, a2 = 0.f, a3 = 0.f;
    float a4 = 0.f, a5 = 0.f, a6 = 0.f, a7 = 0.f;
    float denom = 0.f;

    int j = beg;
    // main loop: 4 independent gathers in flight
    for (; j + 4 <= end; j += 4) {
        int s0 = g_csr_src[j + 0];
        int s1 = g_csr_src[j + 1];
        int s2 = g_csr_src[j + 2];
        int s3 = g_csr_src[j + 3];
        float e0 = g_csr_ee[(size_t)(j + 0) * 4 + h];
        float e1 = g_csr_ee[(size_t)(j + 1) * 4 + h];
        float e2 = g_csr_ee[(size_t)(j + 2) * 4 + h];
        float e3 = g_csr_ee[(size_t)(j + 3) * 4 + h];
        uint4 u0 = *reinterpret_cast<const uint4*>(g_xph + (size_t)s0 * OUT_DIM + lane * 8);
        uint4 u1 = *reinterpret_cast<const uint4*>(g_xph + (size_t)s1 * OUT_DIM + lane * 8);
        uint4 u2 = *reinterpret_cast<const uint4*>(g_xph + (size_t)s2 * OUT_DIM + lane * 8);
        uint4 u3 = *reinterpret_cast<const uint4*>(g_xph + (size_t)s3 * OUT_DIM + lane * 8);
        denom += (e0 + e1) + (e2 + e3);

        const __half2* p;
        float2 f;
#define ACC_EDGE(U, EW)                                            \
        p = reinterpret_cast<const __half2*>(&U);                  \
        f = __half22float2(p[0]); a0 += EW * f.x; a1 += EW * f.y;  \
        f = __half22float2(p[1]); a2 += EW * f.x; a3 += EW * f.y;  \
        f = __half22float2(p[2]); a4 += EW * f.x; a5 += EW * f.y;  \
        f = __half22float2(p[3]); a6 += EW * f.x; a7 += EW * f.y;
        ACC_EDGE(u0, e0)
        ACC_EDGE(u1, e1)
        ACC_EDGE(u2, e2)
        ACC_EDGE(u3, e3)
    }
    // remainder
    for (; j < end; j++) {
        int   s  = g_csr_src[j];
        float ee = g_csr_ee[(size_t)j * 4 + h];
        denom += ee;
        uint4 u = *reinterpret_cast<const uint4*>(g_xph + (size_t)s * OUT_DIM + lane * 8);
        const __half2* p;
        float2 f;
        ACC_EDGE(u, ee)
    }
#undef ACC_EDGE

    float inv = 1.f / denom;
    float4 o0 = make_float4(fmaxf(a0 * inv, 0.f), fmaxf(a1 * inv, 0.f),
                            fmaxf(a2 * inv, 0.f), fmaxf(a3 * inv, 0.f));
    float4 o1 = make_float4(fmaxf(a4 * inv, 0.f), fmaxf(a5 * inv, 0.f),
                            fmaxf(a6 * inv, 0.f), fmaxf(a7 * inv, 0.f));
    float4* op = reinterpret_cast<float4*>(out + (size_t)d * OUT_DIM + lane * 8);
    op[0] = o0;
    op[1] = o1;
}

// ---------------- launch ----------------------------------------------------
extern "C" void kernel_launch(void* const* d_in, const int* in_sizes, int n_in,
                              void* d_out, int out_size)
{
    const float* x       = (const float*)d_in[0];
    const void*  ei      = d_in[1];
    const float* Wm      = (const float*)d_in[2];
    const float* att_src = (const float*)d_in[3];
    const float* att_dst = (const float*)d_in[4];
    float*       out     = (float*)d_out;

    detect_dtype_kernel<<<1, 32>>>((const int*)ei);
    zero_deg_kernel<<<(N_NODES + 255) / 256, 256>>>();
    fold_att_kernel<<<8, 256>>>(Wm, att_src, att_dst);

    attn_gemv_kernel<<<(N_NODES * 32 + 255) / 256, 256>>>(x);

    dim3 ggrid((N_NODES + GBM - 1) / GBM, OUT_DIM / GBN);
    gemm_tf32_kernel<<<ggrid, 256>>>(x, Wm);

    hist_kernel<<<(E_TOT + 255) / 256, 256>>>(ei);
    scan_kernel<<<1, SCAN_T>>>();
    scatter_kernel<<<(E_TOT + 255) / 256, 256>>>(ei);

    aggregate_csr_kernel<<<((size_t)N_NODES * 32 + 255) / 256, 256>>>(out);
}

// round 7
// speedup vs baseline: 1.2543x; 1.2543x over previous
#include <cuda_runtime.h>
#include <cuda_fp16.h>
#include <cstdint>

#define N_NODES 50000
#define N_EDGES 800000
#define E_TOT   (N_EDGES + N_NODES)
#define IN_DIM  256
#define OUT_DIM 256   // N_HEADS * HEAD_DIM
#define NEG_SLOPE 0.2f

// ---------------- scratch (static device globals; no runtime allocation) ---
__device__ __align__(16) __half g_xph[(size_t)N_NODES * OUT_DIM]; // projected features, fp16 [N,256]
__device__ __align__(16) float g_WaT[8 * IN_DIM];                 // folded attn weights, TRANSPOSED [8][256]
__device__ __align__(16) float g_asrc[N_NODES * 4];               // per-node src logits [N,4]
__device__ __align__(16) float g_adst[N_NODES * 4];               // per-node dst logits [N,4]
__device__ __align__(16) float g_csr_ee[(size_t)E_TOT * 4];       // exp(logit), CSR order [E+N,4]
__device__ int g_csr_src[E_TOT];                                  // src node id, CSR order
__device__ int g_deg[N_NODES];                                    // in-degree histogram
__device__ int g_off[N_NODES];                                    // CSR row start
__device__ int g_cur[N_NODES];                                    // scatter cursor -> row end
__device__ int g_is64;                                            // edge_index dtype flag

// ---------------- helpers --------------------------------------------------
__device__ __forceinline__ uint32_t f2tf32(float f) {
    uint32_t r;
    asm("cvt.rna.tf32.f32 %0, %1;" : "=r"(r) : "f"(f));
    return r;
}

__device__ __forceinline__ void load_edge(const void* ei, int i, int& s, int& d) {
    if (g_is64) {
        const long long* p = (const long long*)ei;
        s = (int)p[i];
        d = (int)p[N_EDGES + i];
    } else {
        const int* p = (const int*)ei;
        s = p[i];
        d = p[N_EDGES + i];
    }
}

// ---------------- K-1: dtype detection -------------------------------------
__global__ void detect_dtype_kernel(const int* __restrict__ ei32) {
    if (threadIdx.x == 0 && blockIdx.x == 0) {
        int any = 0;
        for (int k = 0; k < 128; k++) any |= ei32[2 * k + 1];
        g_is64 = (any == 0) ? 1 : 0;
    }
}

// ---------------- K0: zero degree histogram --------------------------------
__global__ void zero_deg_kernel() {
    int i = blockIdx.x * blockDim.x + threadIdx.x;
    if (i < N_NODES) g_deg[i] = 0;
}

// ---------------- K0b: fold att vectors into W (transposed output) ---------
// WaT[h][k]   = sum_c W[k][h*64+c] * att_src[h][c]   (h = 0..3)
// WaT[h+4][k] = sum_c W[k][h*64+c] * att_dst[h][c]
__global__ __launch_bounds__(256) void fold_att_kernel(
    const float* __restrict__ Wm,
    const float* __restrict__ att_src, const float* __restrict__ att_dst)
{
    int idx = blockIdx.x * blockDim.x + threadIdx.x;   // 0..2047
    if (idx >= IN_DIM * 8) return;
    int k = idx >> 3;
    int o = idx & 7;
    int h = o & 3;
    const float* att = (o < 4) ? att_src : att_dst;
    const float* wrow = Wm + (size_t)k * OUT_DIM + h * 64;
    float s = 0.f;
#pragma unroll 16
    for (int c = 0; c < 64; c++) s += wrow[c] * att[h * 64 + c];
    g_WaT[o * IN_DIM + k] = s;
}

// ---------------- K1: GEMM xp = x @ W  (tf32 mma.sync, fp16 output) --------
#define GBM 128
#define GBN 128
#define GBK 32
#define A_LD (GBK + 4)
#define B_LD (GBN + 4)

__global__ __launch_bounds__(256) void gemm_tf32_kernel(
    const float* __restrict__ X, const float* __restrict__ Wm)
{
    __shared__ uint32_t As[GBM][A_LD];
    __shared__ uint32_t Bs[GBK][B_LD];

    const int tid  = threadIdx.x;
    const int wid  = tid >> 5;
    const int lane = tid & 31;
    const int m0 = blockIdx.x * GBM;
    const int n0 = blockIdx.y * GBN;
    const int wm = (wid & 1) * 64;
    const int wn = (wid >> 1) * 32;
    const int gID = lane >> 2;
    const int tig = lane & 3;

    float c[4][4][4];
#pragma unroll
    for (int i = 0; i < 4; i++)
#pragma unroll
        for (int j = 0; j < 4; j++)
#pragma unroll
            for (int r = 0; r < 4; r++) c[i][j][r] = 0.f;

    for (int k0 = 0; k0 < IN_DIM; k0 += GBK) {
#pragma unroll
        for (int l = 0; l < 4; l++) {
            int idx = tid + l * 256;
            int row = idx >> 3;
            int c4  = idx & 7;
            int gm  = m0 + row;
            float4 v = make_float4(0.f, 0.f, 0.f, 0.f);
            if (gm < N_NODES)
                v = *reinterpret_cast<const float4*>(X + (size_t)gm * IN_DIM + k0 + c4 * 4);
            As[row][c4 * 4 + 0] = f2tf32(v.x);
            As[row][c4 * 4 + 1] = f2tf32(v.y);
            As[row][c4 * 4 + 2] = f2tf32(v.z);
            As[row][c4 * 4 + 3] = f2tf32(v.w);
        }
#pragma unroll
        for (int l = 0; l < 4; l++) {
            int idx = tid + l * 256;
            int kr = idx >> 5;
            int c4 = idx & 31;
            float4 v = *reinterpret_cast<const float4*>(
                Wm + (size_t)(k0 + kr) * OUT_DIM + n0 + c4 * 4);
            Bs[kr][c4 * 4 + 0] = f2tf32(v.x);
            Bs[kr][c4 * 4 + 1] = f2tf32(v.y);
            Bs[kr][c4 * 4 + 2] = f2tf32(v.z);
            Bs[kr][c4 * 4 + 3] = f2tf32(v.w);
        }
        __syncthreads();

#pragma unroll
        for (int ks = 0; ks < 4; ks++) {
            const int kb = ks * 8;
            uint32_t a[4][4], b[4][2];
#pragma unroll
            for (int mt = 0; mt < 4; mt++) {
                int rb = wm + mt * 16;
                a[mt][0] = As[rb + gID    ][kb + tig    ];
                a[mt][1] = As[rb + gID + 8][kb + tig    ];
                a[mt][2] = As[rb + gID    ][kb + tig + 4];
                a[mt][3] = As[rb + gID + 8][kb + tig + 4];
            }
#pragma unroll
            for (int nt = 0; nt < 4; nt++) {
                int col = wn + nt * 8 + gID;
                b[nt][0] = Bs[kb + tig    ][col];
                b[nt][1] = Bs[kb + tig + 4][col];
            }
#pragma unroll
            for (int mt = 0; mt < 4; mt++)
#pragma unroll
                for (int nt = 0; nt < 4; nt++) {
                    asm volatile(
                        "mma.sync.aligned.m16n8k8.row.col.f32.tf32.tf32.f32 "
                        "{%0,%1,%2,%3}, {%4,%5,%6,%7}, {%8,%9}, {%0,%1,%2,%3};"
                        : "+f"(c[mt][nt][0]), "+f"(c[mt][nt][1]),
                          "+f"(c[mt][nt][2]), "+f"(c[mt][nt][3])
                        : "r"(a[mt][0]), "r"(a[mt][1]), "r"(a[mt][2]), "r"(a[mt][3]),
                          "r"(b[nt][0]), "r"(b[nt][1]));
                }
        }
        __syncthreads();
    }

#pragma unroll
    for (int mt = 0; mt < 4; mt++) {
        int r0 = m0 + wm + mt * 16 + gID;
#pragma unroll
        for (int nt = 0; nt < 4; nt++) {
            int col = n0 + wn + nt * 8 + 2 * tig;
            if (r0 < N_NODES) {
                __half2 v01 = __floats2half2_rn(c[mt][nt][0], c[mt][nt][1]);
                *reinterpret_cast<__half2*>(g_xph + (size_t)r0 * OUT_DIM + col) = v01;
            }
            if (r0 + 8 < N_NODES) {
                __half2 v23 = __floats2half2_rn(c[mt][nt][2], c[mt][nt][3]);
                *reinterpret_cast<__half2*>(g_xph + (size_t)(r0 + 8) * OUT_DIM + col) = v23;
            }
        }
    }
}

// ---------------- K2: attention logits x @ WaT (register-resident GEMV) ----
// Warp-per-node grid-stride loop. Wa kept in registers: w[o][i] for
// k = lane + 32*i. x read coalesced at the same k. No shared memory at all.
__global__ __launch_bounds__(256) void attn_gemv_kernel(const float* __restrict__ X)
{
    const int lane = threadIdx.x & 31;

    float w[8][8];
#pragma unroll
    for (int o = 0; o < 8; o++)
#pragma unroll
        for (int i = 0; i < 8; i++)
            w[o][i] = g_WaT[o * IN_DIM + 32 * i + lane];

    int warpG  = (blockIdx.x * blockDim.x + threadIdx.x) >> 5;
    int nWarps = (gridDim.x * blockDim.x) >> 5;

    for (int n = warpG; n < N_NODES; n += nWarps) {
        float xv[8];
#pragma unroll
        for (int i = 0; i < 8; i++)
            xv[i] = X[(size_t)n * IN_DIM + 32 * i + lane];

        float acc[8];
#pragma unroll
        for (int o = 0; o < 8; o++) {
            float s = 0.f;
#pragma unroll
            for (int i = 0; i < 8; i++) s += xv[i] * w[o][i];
            acc[o] = s;
        }
#pragma unroll
        for (int off = 16; off > 0; off >>= 1)
#pragma unroll
            for (int o = 0; o < 8; o++)
                acc[o] += __shfl_down_sync(0xffffffffu, acc[o], off);

        if (lane == 0) {
            *reinterpret_cast<float4*>(g_asrc + n * 4) =
                make_float4(acc[0], acc[1], acc[2], acc[3]);
            *reinterpret_cast<float4*>(g_adst + n * 4) =
                make_float4(acc[4], acc[5], acc[6], acc[7]);
        }
    }
}

// ---------------- K3a: in-degree histogram ---------------------------------
__global__ __launch_bounds__(256) void hist_kernel(const void* __restrict__ ei)
{
    int i = blockIdx.x * blockDim.x + threadIdx.x;
    if (i >= E_TOT) return;
    int s, d;
    if (i < N_EDGES) load_edge(ei, i, s, d);
    else             d = i - N_EDGES;
    atomicAdd(&g_deg[d], 1);
}

// ---------------- K3b: single-block exclusive scan -> offsets + cursors ----
#define SCAN_T 1024
__global__ __launch_bounds__(SCAN_T) void scan_kernel()
{
    __shared__ int sums[SCAN_T];
    const int t = threadIdx.x;
    const int CH = (N_NODES + SCAN_T - 1) / SCAN_T;   // 49
    const int lo = t * CH;
    const int hi = (lo + CH < N_NODES) ? lo + CH : N_NODES;

    int s = 0;
    for (int i = lo; i < hi; i++) s += g_deg[i];
    sums[t] = s;
    __syncthreads();

    for (int off = 1; off < SCAN_T; off <<= 1) {
        int v = (t >= off) ? sums[t - off] : 0;
        __syncthreads();
        sums[t] += v;
        __syncthreads();
    }

    int run = (t == 0) ? 0 : sums[t - 1];
    for (int i = lo; i < hi; i++) {
        int dg = g_deg[i];
        g_off[i] = run;
        g_cur[i] = run;
        run += dg;
    }
}

// ---------------- K3c: scatter edges into CSR order + compute exp(logit) ---
__global__ __launch_bounds__(256) void scatter_kernel(const void* __restrict__ ei)
{
    int i = blockIdx.x * blockDim.x + threadIdx.x;
    if (i >= E_TOT) return;
    int s, d;
    if (i < N_EDGES) load_edge(ei, i, s, d);
    else             s = d = i - N_EDGES;   // self-loop

    float4 as = *reinterpret_cast<const float4*>(g_asrc + s * 4);
    float4 ad = *reinterpret_cast<const float4*>(g_adst + d * 4);
    float e0 = as.x + ad.x, e1 = as.y + ad.y, e2 = as.z + ad.z, e3 = as.w + ad.w;
    e0 = (e0 > 0.f) ? e0 : NEG_SLOPE * e0;
    e1 = (e1 > 0.f) ? e1 : NEG_SLOPE * e1;
    e2 = (e2 > 0.f) ? e2 : NEG_SLOPE * e2;
    e3 = (e3 > 0.f) ? e3 : NEG_SLOPE * e3;
    float4 ee = make_float4(__expf(e0), __expf(e1), __expf(e2), __expf(e3));

    int pos = atomicAdd(&g_cur[d], 1);
    g_csr_src[pos] = s;
    *reinterpret_cast<float4*>(g_csr_ee + (size_t)pos * 4) = ee;
}

// ---------------- K4: CSR aggregate, software-pipelined, fused epilogue ----
// One warp per dst node. Double-buffered quads: next batch's loads issue
// before current batch is consumed, overlapping gather latency with math.
__global__ __launch_bounds__(256) void aggregate_csr_kernel(float* __restrict__ out)
{
    int d = (blockIdx.x * blockDim.x + threadIdx.x) >> 5;
    if (d >= N_NODES) return;
    int lane = threadIdx.x & 31;
    int h = lane >> 3;
    int beg = g_off[d];
    int end = g_cur[d];
    const size_t laneOff = (size_t)lane * 8;

    float a0 = 0.f, a1 = 0.f, a2 = 0.f, a3 = 0.f;
    float a4 = 0.f, a5 = 0.f, a6 = 0.f, a7 = 0.f;
    float denom = 0.f;

#define GATHER(S) (*reinterpret_cast<const uint4*>(g_xph + (size_t)(S) * OUT_DIM + laneOff))
#define ACC_EDGE(U, EW) do {                                                   \
        const __half2* p = reinterpret_cast<const __half2*>(&(U));             \
        float2 f;                                                              \
        f = __half22float2(p[0]); a0 += (EW) * f.x; a1 += (EW) * f.y;          \
        f = __half22float2(p[1]); a2 += (EW) * f.x; a3 += (EW) * f.y;          \
        f = __half22float2(p[2]); a4 += (EW) * f.x; a5 += (EW) * f.y;          \
        f = __half22float2(p[3]); a6 += (EW) * f.x; a7 += (EW) * f.y;          \
    } while (0)

    int j = beg;
    if (end - beg >= 4) {
        // prologue: fill buffer A
        int   s0 = g_csr_src[j + 0], s1 = g_csr_src[j + 1];
        int   s2 = g_csr_src[j + 2], s3 = g_csr_src[j + 3];
        float e0 = g_csr_ee[(size_t)(j + 0) * 4 + h];
        float e1 = g_csr_ee[(size_t)(j + 1) * 4 + h];
        float e2 = g_csr_ee[(size_t)(j + 2) * 4 + h];
        float e3 = g_csr_ee[(size_t)(j + 3) * 4 + h];
        uint4 u0 = GATHER(s0), u1 = GATHER(s1), u2 = GATHER(s2), u3 = GATHER(s3);
        j += 4;

        for (; j + 4 <= end; j += 4) {
            // issue buffer B loads BEFORE consuming A
            int   t0 = g_csr_src[j + 0], t1 = g_csr_src[j + 1];
            int   t2 = g_csr_src[j + 2], t3 = g_csr_src[j + 3];
            float f0 = g_csr_ee[(size_t)(j + 0) * 4 + h];
            float f1 = g_csr_ee[(size_t)(j + 1) * 4 + h];
            float f2 = g_csr_ee[(size_t)(j + 2) * 4 + h];
            float f3 = g_csr_ee[(size_t)(j + 3) * 4 + h];
            uint4 v0 = GATHER(t0), v1 = GATHER(t1), v2 = GATHER(t2), v3 = GATHER(t3);

            // consume A
            denom += (e0 + e1) + (e2 + e3);
            ACC_EDGE(u0, e0); ACC_EDGE(u1, e1); ACC_EDGE(u2, e2); ACC_EDGE(u3, e3);

            // B -> A (register renames)
            e0 = f0; e1 = f1; e2 = f2; e3 = f3;
            u0 = v0; u1 = v1; u2 = v2; u3 = v3;
        }
        // epilogue: consume last A
        denom += (e0 + e1) + (e2 + e3);
        ACC_EDGE(u0, e0); ACC_EDGE(u1, e1); ACC_EDGE(u2, e2); ACC_EDGE(u3, e3);
    }
    // tail (< 4 edges)
    for (; j < end; j++) {
        int   s  = g_csr_src[j];
        float ee = g_csr_ee[(size_t)j * 4 + h];
        denom += ee;
        uint4 u = GATHER(s);
        ACC_EDGE(u, ee);
    }
#undef ACC_EDGE
#undef GATHER

    float inv = 1.f / denom;
    float4 o0 = make_float4(fmaxf(a0 * inv, 0.f), fmaxf(a1 * inv, 0.f),
                            fmaxf(a2 * inv, 0.f), fmaxf(a3 * inv, 0.f));
    float4 o1 = make_float4(fmaxf(a4 * inv, 0.f), fmaxf(a5 * inv, 0.f),
                            fmaxf(a6 * inv, 0.f), fmaxf(a7 * inv, 0.f));
    float4* op = reinterpret_cast<float4*>(out + (size_t)d * OUT_DIM + lane * 8);
    op[0] = o0;
    op[1] = o1;
}

// ---------------- launch ----------------------------------------------------
extern "C" void kernel_launch(void* const* d_in, const int* in_sizes, int n_in,
                              void* d_out, int out_size)
{
    const float* x       = (const float*)d_in[0];
    const void*  ei      = d_in[1];
    const float* Wm      = (const float*)d_in[2];
    const float* att_src = (const float*)d_in[3];
    const float* att_dst = (const float*)d_in[4];
    float*       out     = (float*)d_out;

    detect_dtype_kernel<<<1, 32>>>((const int*)ei);
    zero_deg_kernel<<<(N_NODES + 255) / 256, 256>>>();
    fold_att_kernel<<<8, 256>>>(Wm, att_src, att_dst);

    attn_gemv_kernel<<<1184, 256>>>(x);

    dim3 ggrid((N_NODES + GBM - 1) / GBM, OUT_DIM / GBN);
    gemm_tf32_kernel<<<ggrid, 256>>>(x, Wm);

    hist_kernel<<<(E_TOT + 255) / 256, 256>>>(ei);
    scan_kernel<<<1, SCAN_T>>>();
    scatter_kernel<<<(E_TOT + 255) / 256, 256>>>(ei);

    aggregate_csr_kernel<<<((size_t)N_NODES * 32 + 255) / 256, 256>>>(out);
}

// round 8
// speedup vs baseline: 1.7336x; 1.3822x over previous
#include <cuda_runtime.h>
#include <cuda_fp16.h>
#include <cstdint>

#define N_NODES 50000
#define N_EDGES 800000
#define E_TOT   (N_EDGES + N_NODES)
#define IN_DIM  256
#define OUT_DIM 256   // N_HEADS * HEAD_DIM
#define NEG_SLOPE 0.2f
#define NBLK_SCAN ((N_NODES + 255) / 256)   // 196

// ---------------- scratch (static device globals; no runtime allocation) ---
__device__ __align__(16) __half g_xph[(size_t)N_NODES * OUT_DIM]; // projected features, fp16 [N,256]
__device__ __align__(16) float g_WaT[8 * IN_DIM];                 // folded attn weights, transposed [8][256]
__device__ __align__(16) float g_asrc[N_NODES * 4];               // per-node src logits [N,4]
__device__ __align__(16) float g_adst[N_NODES * 4];               // per-node dst logits [N,4]
__device__ __align__(16) float g_csr_ee[(size_t)E_TOT * 4];       // exp(logit), CSR order [E+N,4]
__device__ int g_csr_src[E_TOT];                                  // src node id, CSR order
__device__ int g_deg[N_NODES];                                    // in-degree histogram
__device__ int g_off[N_NODES];                                    // CSR row start
__device__ int g_cur[N_NODES];                                    // scatter cursor -> row end
__device__ int g_bsum[NBLK_SCAN];                                 // per-block degree sums
__device__ int g_boff[NBLK_SCAN];                                 // exclusive-scanned block offsets
__device__ int g_is64;                                            // edge_index dtype flag

// ---------------- helpers --------------------------------------------------
__device__ __forceinline__ uint32_t f2tf32(float f) {
    uint32_t r;
    asm("cvt.rna.tf32.f32 %0, %1;" : "=r"(r) : "f"(f));
    return r;
}

__device__ __forceinline__ void load_edge(const void* ei, int i, int& s, int& d) {
    if (g_is64) {
        const long long* p = (const long long*)ei;
        s = (int)p[i];
        d = (int)p[N_EDGES + i];
    } else {
        const int* p = (const int*)ei;
        s = p[i];
        d = p[N_EDGES + i];
    }
}

// ---------------- K-1: dtype detection -------------------------------------
__global__ void detect_dtype_kernel(const int* __restrict__ ei32) {
    if (threadIdx.x == 0 && blockIdx.x == 0) {
        int any = 0;
        for (int k = 0; k < 128; k++) any |= ei32[2 * k + 1];
        g_is64 = (any == 0) ? 1 : 0;
    }
}

// ---------------- K0: zero degree histogram --------------------------------
__global__ void zero_deg_kernel() {
    int i = blockIdx.x * blockDim.x + threadIdx.x;
    if (i < N_NODES) g_deg[i] = 0;
}

// ---------------- K0b: fold att vectors into W (transposed output) ---------
__global__ __launch_bounds__(256) void fold_att_kernel(
    const float* __restrict__ Wm,
    const float* __restrict__ att_src, const float* __restrict__ att_dst)
{
    int idx = blockIdx.x * blockDim.x + threadIdx.x;   // 0..2047
    if (idx >= IN_DIM * 8) return;
    int k = idx >> 3;
    int o = idx & 7;
    int h = o & 3;
    const float* att = (o < 4) ? att_src : att_dst;
    const float* wrow = Wm + (size_t)k * OUT_DIM + h * 64;
    float s = 0.f;
#pragma unroll 16
    for (int c = 0; c < 64; c++) s += wrow[c] * att[h * 64 + c];
    g_WaT[o * IN_DIM + k] = s;
}

// ---------------- K1: GEMM xp = x @ W  (tf32 mma.sync, fp16 output) --------
#define GBM 128
#define GBN 128
#define GBK 32
#define A_LD (GBK + 4)
#define B_LD (GBN + 4)

__global__ __launch_bounds__(256) void gemm_tf32_kernel(
    const float* __restrict__ X, const float* __restrict__ Wm)
{
    __shared__ uint32_t As[GBM][A_LD];
    __shared__ uint32_t Bs[GBK][B_LD];

    const int tid  = threadIdx.x;
    const int wid  = tid >> 5;
    const int lane = tid & 31;
    const int m0 = blockIdx.x * GBM;
    const int n0 = blockIdx.y * GBN;
    const int wm = (wid & 1) * 64;
    const int wn = (wid >> 1) * 32;
    const int gID = lane >> 2;
    const int tig = lane & 3;

    float c[4][4][4];
#pragma unroll
    for (int i = 0; i < 4; i++)
#pragma unroll
        for (int j = 0; j < 4; j++)
#pragma unroll
            for (int r = 0; r < 4; r++) c[i][j][r] = 0.f;

    for (int k0 = 0; k0 < IN_DIM; k0 += GBK) {
#pragma unroll
        for (int l = 0; l < 4; l++) {
            int idx = tid + l * 256;
            int row = idx >> 3;
            int c4  = idx & 7;
            int gm  = m0 + row;
            float4 v = make_float4(0.f, 0.f, 0.f, 0.f);
            if (gm < N_NODES)
                v = *reinterpret_cast<const float4*>(X + (size_t)gm * IN_DIM + k0 + c4 * 4);
            As[row][c4 * 4 + 0] = f2tf32(v.x);
            As[row][c4 * 4 + 1] = f2tf32(v.y);
            As[row][c4 * 4 + 2] = f2tf32(v.z);
            As[row][c4 * 4 + 3] = f2tf32(v.w);
        }
#pragma unroll
        for (int l = 0; l < 4; l++) {
            int idx = tid + l * 256;
            int kr = idx >> 5;
            int c4 = idx & 31;
            float4 v = *reinterpret_cast<const float4*>(
                Wm + (size_t)(k0 + kr) * OUT_DIM + n0 + c4 * 4);
            Bs[kr][c4 * 4 + 0] = f2tf32(v.x);
            Bs[kr][c4 * 4 + 1] = f2tf32(v.y);
            Bs[kr][c4 * 4 + 2] = f2tf32(v.z);
            Bs[kr][c4 * 4 + 3] = f2tf32(v.w);
        }
        __syncthreads();

#pragma unroll
        for (int ks = 0; ks < 4; ks++) {
            const int kb = ks * 8;
            uint32_t a[4][4], b[4][2];
#pragma unroll
            for (int mt = 0; mt < 4; mt++) {
                int rb = wm + mt * 16;
                a[mt][0] = As[rb + gID    ][kb + tig    ];
                a[mt][1] = As[rb + gID + 8][kb + tig    ];
                a[mt][2] = As[rb + gID    ][kb + tig + 4];
                a[mt][3] = As[rb + gID + 8][kb + tig + 4];
            }
#pragma unroll
            for (int nt = 0; nt < 4; nt++) {
                int col = wn + nt * 8 + gID;
                b[nt][0] = Bs[kb + tig    ][col];
                b[nt][1] = Bs[kb + tig + 4][col];
            }
#pragma unroll
            for (int mt = 0; mt < 4; mt++)
#pragma unroll
                for (int nt = 0; nt < 4; nt++) {
                    asm volatile(
                        "mma.sync.aligned.m16n8k8.row.col.f32.tf32.tf32.f32 "
                        "{%0,%1,%2,%3}, {%4,%5,%6,%7}, {%8,%9}, {%0,%1,%2,%3};"
                        : "+f"(c[mt][nt][0]), "+f"(c[mt][nt][1]),
                          "+f"(c[mt][nt][2]), "+f"(c[mt][nt][3])
                        : "r"(a[mt][0]), "r"(a[mt][1]), "r"(a[mt][2]), "r"(a[mt][3]),
                          "r"(b[nt][0]), "r"(b[nt][1]));
                }
        }
        __syncthreads();
    }

#pragma unroll
    for (int mt = 0; mt < 4; mt++) {
        int r0 = m0 + wm + mt * 16 + gID;
#pragma unroll
        for (int nt = 0; nt < 4; nt++) {
            int col = n0 + wn + nt * 8 + 2 * tig;
            if (r0 < N_NODES) {
                __half2 v01 = __floats2half2_rn(c[mt][nt][0], c[mt][nt][1]);
                *reinterpret_cast<__half2*>(g_xph + (size_t)r0 * OUT_DIM + col) = v01;
            }
            if (r0 + 8 < N_NODES) {
                __half2 v23 = __floats2half2_rn(c[mt][nt][2], c[mt][nt][3]);
                *reinterpret_cast<__half2*>(g_xph + (size_t)(r0 + 8) * OUT_DIM + col) = v23;
            }
        }
    }
}

// ---------------- K2: attention logits x @ WaT (register-resident GEMV) ----
__global__ __launch_bounds__(256) void attn_gemv_kernel(const float* __restrict__ X)
{
    const int lane = threadIdx.x & 31;

    float w[8][8];
#pragma unroll
    for (int o = 0; o < 8; o++)
#pragma unroll
        for (int i = 0; i < 8; i++)
            w[o][i] = g_WaT[o * IN_DIM + 32 * i + lane];

    int warpG  = (blockIdx.x * blockDim.x + threadIdx.x) >> 5;
    int nWarps = (gridDim.x * blockDim.x) >> 5;

    for (int n = warpG; n < N_NODES; n += nWarps) {
        float xv[8];
#pragma unroll
        for (int i = 0; i < 8; i++)
            xv[i] = X[(size_t)n * IN_DIM + 32 * i + lane];

        float acc[8];
#pragma unroll
        for (int o = 0; o < 8; o++) {
            float s = 0.f;
#pragma unroll
            for (int i = 0; i < 8; i++) s += xv[i] * w[o][i];
            acc[o] = s;
        }
#pragma unroll
        for (int off = 16; off > 0; off >>= 1)
#pragma unroll
            for (int o = 0; o < 8; o++)
                acc[o] += __shfl_down_sync(0xffffffffu, acc[o], off);

        if (lane == 0) {
            *reinterpret_cast<float4*>(g_asrc + n * 4) =
                make_float4(acc[0], acc[1], acc[2], acc[3]);
            *reinterpret_cast<float4*>(g_adst + n * 4) =
                make_float4(acc[4], acc[5], acc[6], acc[7]);
        }
    }
}

// ---------------- K3a: in-degree histogram ---------------------------------
__global__ __launch_bounds__(256) void hist_kernel(const void* __restrict__ ei)
{
    int i = blockIdx.x * blockDim.x + threadIdx.x;
    if (i >= E_TOT) return;
    int s, d;
    if (i < N_EDGES) load_edge(ei, i, s, d);
    else             d = i - N_EDGES;
    atomicAdd(&g_deg[d], 1);
}

// ---------------- K3b: coalesced 3-phase exclusive scan --------------------
// Phase 1: per-block (256-wide) exclusive scan of degrees; block sums out.
__global__ __launch_bounds__(256) void scan1_kernel()
{
    __shared__ int sm[256];
    int tid = threadIdx.x;
    int i = blockIdx.x * 256 + tid;
    int v = (i < N_NODES) ? g_deg[i] : 0;
    sm[tid] = v;
    __syncthreads();
#pragma unroll
    for (int off = 1; off < 256; off <<= 1) {
        int t = (tid >= off) ? sm[tid - off] : 0;
        __syncthreads();
        sm[tid] += t;
        __syncthreads();
    }
    int incl = sm[tid];
    if (i < N_NODES) g_off[i] = incl - v;            // local exclusive
    if (tid == 255) g_bsum[blockIdx.x] = incl;       // block total
}

// Phase 2: single block scans the 196 block sums (exclusive).
__global__ __launch_bounds__(256) void scan2_kernel()
{
    __shared__ int sm[256];
    int tid = threadIdx.x;
    int v = (tid < NBLK_SCAN) ? g_bsum[tid] : 0;
    sm[tid] = v;
    __syncthreads();
#pragma unroll
    for (int off = 1; off < 256; off <<= 1) {
        int t = (tid >= off) ? sm[tid - off] : 0;
        __syncthreads();
        sm[tid] += t;
        __syncthreads();
    }
    if (tid < NBLK_SCAN) g_boff[tid] = sm[tid] - v;  // exclusive
}

// Phase 3: add block offsets; init cursors.
__global__ __launch_bounds__(256) void scan3_kernel()
{
    int i = blockIdx.x * 256 + threadIdx.x;
    if (i < N_NODES) {
        int o = g_off[i] + g_boff[blockIdx.x];
        g_off[i] = o;
        g_cur[i] = o;
    }
}

// ---------------- K3c: scatter edges into CSR order + compute exp(logit) ---
__global__ __launch_bounds__(256) void scatter_kernel(const void* __restrict__ ei)
{
    int i = blockIdx.x * blockDim.x + threadIdx.x;
    if (i >= E_TOT) return;
    int s, d;
    if (i < N_EDGES) load_edge(ei, i, s, d);
    else             s = d = i - N_EDGES;   // self-loop

    float4 as = *reinterpret_cast<const float4*>(g_asrc + s * 4);
    float4 ad = *reinterpret_cast<const float4*>(g_adst + d * 4);
    float e0 = as.x + ad.x, e1 = as.y + ad.y, e2 = as.z + ad.z, e3 = as.w + ad.w;
    e0 = (e0 > 0.f) ? e0 : NEG_SLOPE * e0;
    e1 = (e1 > 0.f) ? e1 : NEG_SLOPE * e1;
    e2 = (e2 > 0.f) ? e2 : NEG_SLOPE * e2;
    e3 = (e3 > 0.f) ? e3 : NEG_SLOPE * e3;
    float4 ee = make_float4(__expf(e0), __expf(e1), __expf(e2), __expf(e3));

    int pos = atomicAdd(&g_cur[d], 1);
    g_csr_src[pos] = s;
    *reinterpret_cast<float4*>(g_csr_ee + (size_t)pos * 4) = ee;
}

// ---------------- K4: CSR aggregate (simple loop), fused softmax + ReLU ----
__global__ __launch_bounds__(256) void aggregate_csr_kernel(float* __restrict__ out)
{
    int d = (blockIdx.x * blockDim.x + threadIdx.x) >> 5;
    if (d >= N_NODES) return;
    int lane = threadIdx.x & 31;
    int h = lane >> 3;
    int beg = g_off[d];
    int end = g_cur[d];

    float a0 = 0.f, a1 = 0.f, a2 = 0.f, a3 = 0.f;
    float a4 = 0.f, a5 = 0.f, a6 = 0.f, a7 = 0.f;
    float denom = 0.f;

    for (int j = beg; j < end; j++) {
        int   s  = g_csr_src[j];
        float ee = g_csr_ee[(size_t)j * 4 + h];
        denom += ee;
        uint4 u = *reinterpret_cast<const uint4*>(
            g_xph + (size_t)s * OUT_DIM + lane * 8);
        const __half2* hp = reinterpret_cast<const __half2*>(&u);
        float2 f0 = __half22float2(hp[0]);
        float2 f1 = __half22float2(hp[1]);
        float2 f2 = __half22float2(hp[2]);
        float2 f3 = __half22float2(hp[3]);
        a0 += ee * f0.x; a1 += ee * f0.y;
        a2 += ee * f1.x; a3 += ee * f1.y;
        a4 += ee * f2.x; a5 += ee * f2.y;
        a6 += ee * f3.x; a7 += ee * f3.y;
    }

    float inv = 1.f / denom;
    float4 o0 = make_float4(fmaxf(a0 * inv, 0.f), fmaxf(a1 * inv, 0.f),
                            fmaxf(a2 * inv, 0.f), fmaxf(a3 * inv, 0.f));
    float4 o1 = make_float4(fmaxf(a4 * inv, 0.f), fmaxf(a5 * inv, 0.f),
                            fmaxf(a6 * inv, 0.f), fmaxf(a7 * inv, 0.f));
    float4* op = reinterpret_cast<float4*>(out + (size_t)d * OUT_DIM + lane * 8);
    op[0] = o0;
    op[1] = o1;
}

// ---------------- launch ----------------------------------------------------
extern "C" void kernel_launch(void* const* d_in, const int* in_sizes, int n_in,
                              void* d_out, int out_size)
{
    const float* x       = (const float*)d_in[0];
    const void*  ei      = d_in[1];
    const float* Wm      = (const float*)d_in[2];
    const float* att_src = (const float*)d_in[3];
    const float* att_dst = (const float*)d_in[4];
    float*       out     = (float*)d_out;

    detect_dtype_kernel<<<1, 32>>>((const int*)ei);
    zero_deg_kernel<<<NBLK_SCAN, 256>>>();
    fold_att_kernel<<<8, 256>>>(Wm, att_src, att_dst);

    attn_gemv_kernel<<<1184, 256>>>(x);

    dim3 ggrid((N_NODES + GBM - 1) / GBM, OUT_DIM / GBN);
    gemm_tf32_kernel<<<ggrid, 256>>>(x, Wm);

    hist_kernel<<<(E_TOT + 255) / 256, 256>>>(ei);
    scan1_kernel<<<NBLK_SCAN, 256>>>();
    scan2_kernel<<<1, 256>>>();
    scan3_kernel<<<NBLK_SCAN, 256>>>();
    scatter_kernel<<<(E_TOT + 255) / 256, 256>>>(ei);

    aggregate_csr_kernel<<<((size_t)N_NODES * 32 + 255) / 256, 256>>>(out);
}

// round 9
// speedup vs baseline: 2.0515x; 1.1833x over previous
#include <cuda_runtime.h>
#include <cuda_fp16.h>
#include <cstdint>

#define N_NODES 50000
#define N_EDGES 800000
#define E_TOT   (N_EDGES + N_NODES)
#define IN_DIM  256
#define OUT_DIM 256   // N_HEADS * HEAD_DIM
#define NEG_SLOPE 0.2f
#define NBLK_SCAN ((N_NODES + 255) / 256)   // 196

// ---------------- scratch (static device globals; no runtime allocation) ---
__device__ __align__(16) __half g_xph[(size_t)N_NODES * OUT_DIM]; // projected features, fp16 [N,256]
__device__ __align__(16) float g_asrc[N_NODES * 4];               // per-node src logits [N,4]
__device__ __align__(16) float g_adst[N_NODES * 4];               // per-node dst logits [N,4]
__device__ __align__(16) float g_csr_ee[(size_t)E_TOT * 4];       // exp(logit), CSR order [E+N,4]
__device__ int g_csr_src[E_TOT];                                  // src node id, CSR order
__device__ int g_deg[N_NODES];                                    // in-degree histogram
__device__ int g_off[N_NODES];                                    // CSR row start
__device__ int g_cur[N_NODES];                                    // scatter cursor -> row end
__device__ int g_bsum[NBLK_SCAN];                                 // per-block degree sums
__device__ int g_boff[NBLK_SCAN];                                 // scanned block offsets
__device__ int g_is64;                                            // edge_index dtype flag

// ---------------- helpers --------------------------------------------------
__device__ __forceinline__ uint32_t f2tf32(float f) {
    uint32_t r;
    asm("cvt.rna.tf32.f32 %0, %1;" : "=r"(r) : "f"(f));
    return r;
}

__device__ __forceinline__ void load_edge(const void* ei, int i, int& s, int& d) {
    if (g_is64) {
        const long long* p = (const long long*)ei;
        s = (int)p[i];
        d = (int)p[N_EDGES + i];
    } else {
        const int* p = (const int*)ei;
        s = p[i];
        d = p[N_EDGES + i];
    }
}

// ---------------- K-1: dtype detection -------------------------------------
__global__ void detect_dtype_kernel(const int* __restrict__ ei32) {
    if (threadIdx.x == 0 && blockIdx.x == 0) {
        int any = 0;
        for (int k = 0; k < 128; k++) any |= ei32[2 * k + 1];
        g_is64 = (any == 0) ? 1 : 0;
    }
}

// ---------------- K0: zero degrees + logit accumulators --------------------
__global__ void zero_kernel() {
    int i = blockIdx.x * blockDim.x + threadIdx.x;
    if (i < N_NODES) {
        g_deg[i] = 0;
        float4 z = make_float4(0.f, 0.f, 0.f, 0.f);
        *reinterpret_cast<float4*>(g_asrc + i * 4) = z;
        *reinterpret_cast<float4*>(g_adst + i * 4) = z;
    }
}

// ---------------- K1: GEMM xp = x @ W (tf32 mma, double-buffered, ----------
//                      fused attention-logit epilogue)
#define GBM 128
#define GBN 128
#define GBK 16
#define A_LD (GBK + 4)    // 20
#define B_LD (GBN + 4)    // 132
#define NK_IT (IN_DIM / GBK)   // 16

__global__ __launch_bounds__(256) void gemm_tf32_kernel(
    const float* __restrict__ X, const float* __restrict__ Wm,
    const float* __restrict__ att_src, const float* __restrict__ att_dst)
{
    __shared__ uint32_t As[2][GBM][A_LD];
    __shared__ uint32_t Bs[2][GBK][B_LD];

    const int tid  = threadIdx.x;
    const int wid  = tid >> 5;
    const int lane = tid & 31;
    const int m0 = blockIdx.x * GBM;
    const int n0 = blockIdx.y * GBN;
    const int wm = (wid & 1) * 64;
    const int wn = (wid >> 1) * 32;
    const int gID = lane >> 2;
    const int tig = lane & 3;

    // loader mapping
    const int arow = tid >> 2;          // 0..63 (l=0), +64 (l=1)
    const int ac4  = tid & 3;           // 0..3
    const int brow = tid >> 5;          // 0..7 (l=0), +8 (l=1)
    const int bc4  = tid & 31;          // 0..31

    float4 aP0, aP1, bP0, bP1;

#define LOAD_TILE(K0) do {                                                     \
        int gm0 = m0 + arow;                                                   \
        int gm1 = gm0 + 64;                                                    \
        aP0 = (gm0 < N_NODES) ? *reinterpret_cast<const float4*>(              \
                  X + (size_t)gm0 * IN_DIM + (K0) + ac4 * 4)                   \
                              : make_float4(0.f, 0.f, 0.f, 0.f);               \
        aP1 = (gm1 < N_NODES) ? *reinterpret_cast<const float4*>(              \
                  X + (size_t)gm1 * IN_DIM + (K0) + ac4 * 4)                   \
                              : make_float4(0.f, 0.f, 0.f, 0.f);               \
        bP0 = *reinterpret_cast<const float4*>(                                \
                  Wm + (size_t)((K0) + brow) * OUT_DIM + n0 + bc4 * 4);        \
        bP1 = *reinterpret_cast<const float4*>(                                \
                  Wm + (size_t)((K0) + brow + 8) * OUT_DIM + n0 + bc4 * 4);    \
    } while (0)

#define STORE_TILE(BUF) do {                                                   \
        As[BUF][arow     ][ac4 * 4 + 0] = f2tf32(aP0.x);                       \
        As[BUF][arow     ][ac4 * 4 + 1] = f2tf32(aP0.y);                       \
        As[BUF][arow     ][ac4 * 4 + 2] = f2tf32(aP0.z);                       \
        As[BUF][arow     ][ac4 * 4 + 3] = f2tf32(aP0.w);                       \
        As[BUF][arow + 64][ac4 * 4 + 0] = f2tf32(aP1.x);                       \
        As[BUF][arow + 64][ac4 * 4 + 1] = f2tf32(aP1.y);                       \
        As[BUF][arow + 64][ac4 * 4 + 2] = f2tf32(aP1.z);                       \
        As[BUF][arow + 64][ac4 * 4 + 3] = f2tf32(aP1.w);                       \
        Bs[BUF][brow    ][bc4 * 4 + 0] = f2tf32(bP0.x);                        \
        Bs[BUF][brow    ][bc4 * 4 + 1] = f2tf32(bP0.y);                        \
        Bs[BUF][brow    ][bc4 * 4 + 2] = f2tf32(bP0.z);                        \
        Bs[BUF][brow    ][bc4 * 4 + 3] = f2tf32(bP0.w);                        \
        Bs[BUF][brow + 8][bc4 * 4 + 0] = f2tf32(bP1.x);                        \
        Bs[BUF][brow + 8][bc4 * 4 + 1] = f2tf32(bP1.y);                        \
        Bs[BUF][brow + 8][bc4 * 4 + 2] = f2tf32(bP1.z);                        \
        Bs[BUF][brow + 8][bc4 * 4 + 3] = f2tf32(bP1.w);                        \
    } while (0)

    float c[4][4][4];
#pragma unroll
    for (int i = 0; i < 4; i++)
#pragma unroll
        for (int j = 0; j < 4; j++)
#pragma unroll
            for (int r = 0; r < 4; r++) c[i][j][r] = 0.f;

    LOAD_TILE(0);
    STORE_TILE(0);
    __syncthreads();

    for (int it = 0; it < NK_IT; it++) {
        if (it < NK_IT - 1) LOAD_TILE((it + 1) * GBK);
        const int buf = it & 1;

#pragma unroll
        for (int ks = 0; ks < 2; ks++) {
            const int kb = ks * 8;
            uint32_t a[4][4], b[4][2];
#pragma unroll
            for (int mt = 0; mt < 4; mt++) {
                int rb = wm + mt * 16;
                a[mt][0] = As[buf][rb + gID    ][kb + tig    ];
                a[mt][1] = As[buf][rb + gID + 8][kb + tig    ];
                a[mt][2] = As[buf][rb + gID    ][kb + tig + 4];
                a[mt][3] = As[buf][rb + gID + 8][kb + tig + 4];
            }
#pragma unroll
            for (int nt = 0; nt < 4; nt++) {
                int col = wn + nt * 8 + gID;
                b[nt][0] = Bs[buf][kb + tig    ][col];
                b[nt][1] = Bs[buf][kb + tig + 4][col];
            }
#pragma unroll
            for (int mt = 0; mt < 4; mt++)
#pragma unroll
                for (int nt = 0; nt < 4; nt++) {
                    asm volatile(
                        "mma.sync.aligned.m16n8k8.row.col.f32.tf32.tf32.f32 "
                        "{%0,%1,%2,%3}, {%4,%5,%6,%7}, {%8,%9}, {%0,%1,%2,%3};"
                        : "+f"(c[mt][nt][0]), "+f"(c[mt][nt][1]),
                          "+f"(c[mt][nt][2]), "+f"(c[mt][nt][3])
                        : "r"(a[mt][0]), "r"(a[mt][1]), "r"(a[mt][2]), "r"(a[mt][3]),
                          "r"(b[nt][0]), "r"(b[nt][1]));
                }
        }

        if (it < NK_IT - 1) {
            STORE_TILE(buf ^ 1);
            __syncthreads();
        }
    }
#undef LOAD_TILE
#undef STORE_TILE

    // ---- epilogue 1: fp16 xp stores ----
#pragma unroll
    for (int mt = 0; mt < 4; mt++) {
        int r0 = m0 + wm + mt * 16 + gID;
#pragma unroll
        for (int nt = 0; nt < 4; nt++) {
            int col = n0 + wn + nt * 8 + 2 * tig;
            if (r0 < N_NODES) {
                __half2 v01 = __floats2half2_rn(c[mt][nt][0], c[mt][nt][1]);
                *reinterpret_cast<__half2*>(g_xph + (size_t)r0 * OUT_DIM + col) = v01;
            }
            if (r0 + 8 < N_NODES) {
                __half2 v23 = __floats2half2_rn(c[mt][nt][2], c[mt][nt][3]);
                *reinterpret_cast<__half2*>(g_xph + (size_t)(r0 + 8) * OUT_DIM + col) = v23;
            }
        }
    }

    // ---- epilogue 2: fused attention logits ----
    // Each thread's 8 cols live in exactly one head: h = (n0 + wn) >> 6.
    float psrc0[4], psrc1[4], pdst0[4], pdst1[4];
#pragma unroll
    for (int mt = 0; mt < 4; mt++) {
        psrc0[mt] = psrc1[mt] = pdst0[mt] = pdst1[mt] = 0.f;
#pragma unroll
        for (int nt = 0; nt < 4; nt++) {
            int col = n0 + wn + nt * 8 + 2 * tig;
            float as0 = att_src[col], as1 = att_src[col + 1];
            float ad0 = att_dst[col], ad1 = att_dst[col + 1];
            psrc0[mt] += c[mt][nt][0] * as0 + c[mt][nt][1] * as1;
            psrc1[mt] += c[mt][nt][2] * as0 + c[mt][nt][3] * as1;
            pdst0[mt] += c[mt][nt][0] * ad0 + c[mt][nt][1] * ad1;
            pdst1[mt] += c[mt][nt][2] * ad0 + c[mt][nt][3] * ad1;
        }
    }
    // quad reduction (lanes gID*4 + tig share rows)
#pragma unroll
    for (int off = 1; off <= 2; off <<= 1) {
#pragma unroll
        for (int mt = 0; mt < 4; mt++) {
            psrc0[mt] += __shfl_xor_sync(0xffffffffu, psrc0[mt], off);
            psrc1[mt] += __shfl_xor_sync(0xffffffffu, psrc1[mt], off);
            pdst0[mt] += __shfl_xor_sync(0xffffffffu, pdst0[mt], off);
            pdst1[mt] += __shfl_xor_sync(0xffffffffu, pdst1[mt], off);
        }
    }
    if (tig == 0) {
        int h = (n0 + wn) >> 6;
#pragma unroll
        for (int mt = 0; mt < 4; mt++) {
            int r0 = m0 + wm + mt * 16 + gID;
            if (r0 < N_NODES) {
                atomicAdd(&g_asrc[r0 * 4 + h], psrc0[mt]);
                atomicAdd(&g_adst[r0 * 4 + h], pdst0[mt]);
            }
            if (r0 + 8 < N_NODES) {
                atomicAdd(&g_asrc[(r0 + 8) * 4 + h], psrc1[mt]);
                atomicAdd(&g_adst[(r0 + 8) * 4 + h], pdst1[mt]);
            }
        }
    }
}

// ---------------- K3a: in-degree histogram ---------------------------------
__global__ __launch_bounds__(256) void hist_kernel(const void* __restrict__ ei)
{
    int i = blockIdx.x * blockDim.x + threadIdx.x;
    if (i >= E_TOT) return;
    int s, d;
    if (i < N_EDGES) load_edge(ei, i, s, d);
    else             d = i - N_EDGES;
    atomicAdd(&g_deg[d], 1);
}

// ---------------- K3b: coalesced 3-phase exclusive scan --------------------
__global__ __launch_bounds__(256) void scan1_kernel()
{
    __shared__ int sm[256];
    int tid = threadIdx.x;
    int i = blockIdx.x * 256 + tid;
    int v = (i < N_NODES) ? g_deg[i] : 0;
    sm[tid] = v;
    __syncthreads();
#pragma unroll
    for (int off = 1; off < 256; off <<= 1) {
        int t = (tid >= off) ? sm[tid - off] : 0;
        __syncthreads();
        sm[tid] += t;
        __syncthreads();
    }
    int incl = sm[tid];
    if (i < N_NODES) g_off[i] = incl - v;
    if (tid == 255) g_bsum[blockIdx.x] = incl;
}

__global__ __launch_bounds__(256) void scan2_kernel()
{
    __shared__ int sm[256];
    int tid = threadIdx.x;
    int v = (tid < NBLK_SCAN) ? g_bsum[tid] : 0;
    sm[tid] = v;
    __syncthreads();
#pragma unroll
    for (int off = 1; off < 256; off <<= 1) {
        int t = (tid >= off) ? sm[tid - off] : 0;
        __syncthreads();
        sm[tid] += t;
        __syncthreads();
    }
    if (tid < NBLK_SCAN) g_boff[tid] = sm[tid] - v;
}

__global__ __launch_bounds__(256) void scan3_kernel()
{
    int i = blockIdx.x * 256 + threadIdx.x;
    if (i < N_NODES) {
        int o = g_off[i] + g_boff[blockIdx.x];
        g_off[i] = o;
        g_cur[i] = o;
    }
}

// ---------------- K3c: scatter edges into CSR order + compute exp(logit) ---
__global__ __launch_bounds__(256) void scatter_kernel(const void* __restrict__ ei)
{
    int i = blockIdx.x * blockDim.x + threadIdx.x;
    if (i >= E_TOT) return;
    int s, d;
    if (i < N_EDGES) load_edge(ei, i, s, d);
    else             s = d = i - N_EDGES;   // self-loop

    float4 as = *reinterpret_cast<const float4*>(g_asrc + s * 4);
    float4 ad = *reinterpret_cast<const float4*>(g_adst + d * 4);
    float e0 = as.x + ad.x, e1 = as.y + ad.y, e2 = as.z + ad.z, e3 = as.w + ad.w;
    e0 = (e0 > 0.f) ? e0 : NEG_SLOPE * e0;
    e1 = (e1 > 0.f) ? e1 : NEG_SLOPE * e1;
    e2 = (e2 > 0.f) ? e2 : NEG_SLOPE * e2;
    e3 = (e3 > 0.f) ? e3 : NEG_SLOPE * e3;
    float4 ee = make_float4(__expf(e0), __expf(e1), __expf(e2), __expf(e3));

    int pos = atomicAdd(&g_cur[d], 1);
    g_csr_src[pos] = s;
    *reinterpret_cast<float4*>(g_csr_ee + (size_t)pos * 4) = ee;
}

// ---------------- K4: CSR aggregate (simple loop), fused softmax + ReLU ----
__global__ __launch_bounds__(256) void aggregate_csr_kernel(float* __restrict__ out)
{
    int d = (blockIdx.x * blockDim.x + threadIdx.x) >> 5;
    if (d >= N_NODES) return;
    int lane = threadIdx.x & 31;
    int h = lane >> 3;
    int beg = g_off[d];
    int end = g_cur[d];

    float a0 = 0.f, a1 = 0.f, a2 = 0.f, a3 = 0.f;
    float a4 = 0.f, a5 = 0.f, a6 = 0.f, a7 = 0.f;
    float denom = 0.f;

    for (int j = beg; j < end; j++) {
        int   s  = g_csr_src[j];
        float ee = g_csr_ee[(size_t)j * 4 + h];
        denom += ee;
        uint4 u = *reinterpret_cast<const uint4*>(
            g_xph + (size_t)s * OUT_DIM + lane * 8);
        const __half2* hp = reinterpret_cast<const __half2*>(&u);
        float2 f0 = __half22float2(hp[0]);
        float2 f1 = __half22float2(hp[1]);
        float2 f2 = __half22float2(hp[2]);
        float2 f3 = __half22float2(hp[3]);
        a0 += ee * f0.x; a1 += ee * f0.y;
        a2 += ee * f1.x; a3 += ee * f1.y;
        a4 += ee * f2.x; a5 += ee * f2.y;
        a6 += ee * f3.x; a7 += ee * f3.y;
    }

    float inv = 1.f / denom;
    float4 o0 = make_float4(fmaxf(a0 * inv, 0.f), fmaxf(a1 * inv, 0.f),
                            fmaxf(a2 * inv, 0.f), fmaxf(a3 * inv, 0.f));
    float4 o1 = make_float4(fmaxf(a4 * inv, 0.f), fmaxf(a5 * inv, 0.f),
                            fmaxf(a6 * inv, 0.f), fmaxf(a7 * inv, 0.f));
    float4* op = reinterpret_cast<float4*>(out + (size_t)d * OUT_DIM + lane * 8);
    op[0] = o0;
    op[1] = o1;
}

// ---------------- launch ----------------------------------------------------
extern "C" void kernel_launch(void* const* d_in, const int* in_sizes, int n_in,
                              void* d_out, int out_size)
{
    const float* x       = (const float*)d_in[0];
    const void*  ei      = d_in[1];
    const float* Wm      = (const float*)d_in[2];
    const float* att_src = (const float*)d_in[3];
    const float* att_dst = (const float*)d_in[4];
    float*       out     = (float*)d_out;

    detect_dtype_kernel<<<1, 32>>>((const int*)ei);
    zero_kernel<<<NBLK_SCAN, 256>>>();

    hist_kernel<<<(E_TOT + 255) / 256, 256>>>(ei);
    scan1_kernel<<<NBLK_SCAN, 256>>>();
    scan2_kernel<<<1, 256>>>();
    scan3_kernel<<<NBLK_SCAN, 256>>>();

    dim3 ggrid((N_NODES + GBM - 1) / GBM, OUT_DIM / GBN);
    gemm_tf32_kernel<<<ggrid, 256>>>(x, Wm, att_src, att_dst);

    scatter_kernel<<<(E_TOT + 255) / 256, 256>>>(ei);

    aggregate_csr_kernel<<<((size_t)N_NODES * 32 + 255) / 256, 256>>>(out);
}

// round 10
// speedup vs baseline: 2.2373x; 1.0906x over previous
#include <cuda_runtime.h>
#include <cuda_fp16.h>
#include <cstdint>

#define N_NODES 50000
#define N_EDGES 800000
#define E_TOT   (N_EDGES + N_NODES)
#define IN_DIM  256
#define OUT_DIM 256   // N_HEADS * HEAD_DIM
#define NEG_SLOPE 0.2f
#define NBLK_SCAN ((N_NODES + 255) / 256)   // 196

// ---------------- scratch (static device globals; no runtime allocation) ---
__device__ __align__(16) __half g_xph[(size_t)N_NODES * OUT_DIM]; // projected features, fp16 [N,256]
__device__ __align__(16) float g_asrc[N_NODES * 4];               // per-node src logits [N,4]
__device__ __align__(16) float g_adst[N_NODES * 4];               // per-node dst logits [N,4]
__device__ __align__(16) float g_csr_ee[(size_t)E_TOT * 4];       // exp(logit), CSR order [E+N,4]
__device__ int g_csr_src[E_TOT];                                  // src node id, CSR order
__device__ int g_deg[N_NODES];                                    // in-degree histogram
__device__ int g_off[N_NODES];                                    // CSR row start
__device__ int g_cur[N_NODES];                                    // scatter cursor -> row end
__device__ int g_bsum[NBLK_SCAN];                                 // per-block degree sums
__device__ int g_boff[NBLK_SCAN];                                 // scanned block offsets
__device__ int g_is64;                                            // edge_index dtype flag

// ---------------- helpers --------------------------------------------------
__device__ __forceinline__ uint32_t f2tf32(float f) {
    uint32_t r;
    asm("cvt.rna.tf32.f32 %0, %1;" : "=r"(r) : "f"(f));
    return r;
}

__device__ __forceinline__ void load_edge(const void* ei, int i, int& s, int& d) {
    if (g_is64) {
        const long long* p = (const long long*)ei;
        s = (int)p[i];
        d = (int)p[N_EDGES + i];
    } else {
        const int* p = (const int*)ei;
        s = p[i];
        d = p[N_EDGES + i];
    }
}

// ---------------- K0: zero degrees + logit accumulators + dtype detect -----
__global__ void zero_kernel(const int* __restrict__ ei32) {
    int i = blockIdx.x * blockDim.x + threadIdx.x;
    if (i < N_NODES) {
        g_deg[i] = 0;
        float4 z = make_float4(0.f, 0.f, 0.f, 0.f);
        *reinterpret_cast<float4*>(g_asrc + i * 4) = z;
        *reinterpret_cast<float4*>(g_adst + i * 4) = z;
    }
    if (blockIdx.x == 0 && threadIdx.x == 0) {
        int any = 0;
        for (int k = 0; k < 128; k++) any |= ei32[2 * k + 1];
        g_is64 = (any == 0) ? 1 : 0;
    }
}

// ---------------- K1: GEMM xp = x @ W (tf32 mma, cp.async 3-stage, ---------
//                      fused attention-logit epilogue)
#define GBM 128
#define GBN 128
#define GBK 32
#define NK_IT (IN_DIM / GBK)      // 8
#define A_LD 36                   // floats per A row (conflict-free frags)
#define B_LD 136                  // floats per B row (conflict-free frags)
#define A_STG_B (GBM * A_LD * 4)  // 18432 bytes per A stage
#define B_STG_B (GBK * B_LD * 4)  // 17408 bytes per B stage
#define B_BASE_B (3 * A_STG_B)    // 55296
#define GEMM_SMEM (3 * (A_STG_B + B_STG_B))  // 107520

__global__ __launch_bounds__(256) void gemm_tf32_kernel(
    const float* __restrict__ X, const float* __restrict__ Wm,
    const float* __restrict__ att_src, const float* __restrict__ att_dst)
{
    extern __shared__ char smem_raw[];
    float* Asf = reinterpret_cast<float*>(smem_raw);
    float* Bsf = reinterpret_cast<float*>(smem_raw + B_BASE_B);
    const uint32_t sbase = (uint32_t)__cvta_generic_to_shared(smem_raw);

    const int tid  = threadIdx.x;
    const int wid  = tid >> 5;
    const int lane = tid & 31;
    const int m0 = blockIdx.x * GBM;
    const int n0 = blockIdx.y * GBN;
    const int wm = (wid & 1) * 64;
    const int wn = (wid >> 1) * 32;
    const int gID = lane >> 2;
    const int tig = lane & 3;

#define ISSUE_STAGE(K0, STG) do {                                              \
        _Pragma("unroll")                                                      \
        for (int l = 0; l < 4; l++) {                                          \
            int idx = tid + l * 256;                                           \
            int row = idx >> 3, c4 = idx & 7;                                  \
            int gm = m0 + row;                                                 \
            int sz = (gm < N_NODES) ? 16 : 0;                                  \
            if (gm >= N_NODES) gm = N_NODES - 1;                               \
            uint32_t dst = sbase + (STG) * A_STG_B + row * (A_LD * 4) + c4 * 16;\
            const char* src = (const char*)X + (size_t)gm * (IN_DIM * 4)       \
                              + (K0) * 4 + c4 * 16;                            \
            asm volatile("cp.async.cg.shared.global [%0], [%1], 16, %2;"       \
                         :: "r"(dst), "l"(src), "r"(sz));                      \
        }                                                                      \
        _Pragma("unroll")                                                      \
        for (int l = 0; l < 4; l++) {                                          \
            int idx = tid + l * 256;                                           \
            int kr = idx >> 5, c4 = idx & 31;                                  \
            uint32_t dst = sbase + B_BASE_B + (STG) * B_STG_B                  \
                           + kr * (B_LD * 4) + c4 * 16;                        \
            const char* src = (const char*)Wm                                  \
                + ((size_t)((K0) + kr) * OUT_DIM + n0) * 4 + c4 * 16;          \
            asm volatile("cp.async.cg.shared.global [%0], [%1], 16;"           \
                         :: "r"(dst), "l"(src));                               \
        }                                                                      \
        asm volatile("cp.async.commit_group;" ::: "memory");                   \
    } while (0)

    float c[4][4][4];
#pragma unroll
    for (int i = 0; i < 4; i++)
#pragma unroll
        for (int j = 0; j < 4; j++)
#pragma unroll
            for (int r = 0; r < 4; r++) c[i][j][r] = 0.f;

    // prologue: stages 0 and 1 in flight
    ISSUE_STAGE(0, 0);
    ISSUE_STAGE(GBK, 1);

    for (int it = 0; it < NK_IT; it++) {
        if (it == NK_IT - 1) asm volatile("cp.async.wait_group 0;" ::: "memory");
        else                 asm volatile("cp.async.wait_group 1;" ::: "memory");
        __syncthreads();

        const int stg = it % 3;
        const float* Af = Asf + stg * (GBM * A_LD);
        const float* Bf = Bsf + stg * (GBK * B_LD);

#pragma unroll
        for (int ks = 0; ks < 4; ks++) {
            const int kb = ks * 8;
            uint32_t a[4][4], b[4][2];
#pragma unroll
            for (int mt = 0; mt < 4; mt++) {
                int rb = wm + mt * 16;
                a[mt][0] = f2tf32(Af[(rb + gID    ) * A_LD + kb + tig    ]);
                a[mt][1] = f2tf32(Af[(rb + gID + 8) * A_LD + kb + tig    ]);
                a[mt][2] = f2tf32(Af[(rb + gID    ) * A_LD + kb + tig + 4]);
                a[mt][3] = f2tf32(Af[(rb + gID + 8) * A_LD + kb + tig + 4]);
            }
#pragma unroll
            for (int nt = 0; nt < 4; nt++) {
                int col = wn + nt * 8 + gID;
                b[nt][0] = f2tf32(Bf[(kb + tig    ) * B_LD + col]);
                b[nt][1] = f2tf32(Bf[(kb + tig + 4) * B_LD + col]);
            }
#pragma unroll
            for (int mt = 0; mt < 4; mt++)
#pragma unroll
                for (int nt = 0; nt < 4; nt++) {
                    asm volatile(
                        "mma.sync.aligned.m16n8k8.row.col.f32.tf32.tf32.f32 "
                        "{%0,%1,%2,%3}, {%4,%5,%6,%7}, {%8,%9}, {%0,%1,%2,%3};"
                        : "+f"(c[mt][nt][0]), "+f"(c[mt][nt][1]),
                          "+f"(c[mt][nt][2]), "+f"(c[mt][nt][3])
                        : "r"(a[mt][0]), "r"(a[mt][1]), "r"(a[mt][2]), "r"(a[mt][3]),
                          "r"(b[nt][0]), "r"(b[nt][1]));
                }
        }

        if (it + 2 < NK_IT) {
            ISSUE_STAGE((it + 2) * GBK, (it + 2) % 3);
        }
    }
#undef ISSUE_STAGE

    // ---- epilogue 1: fp16 xp stores ----
#pragma unroll
    for (int mt = 0; mt < 4; mt++) {
        int r0 = m0 + wm + mt * 16 + gID;
#pragma unroll
        for (int nt = 0; nt < 4; nt++) {
            int col = n0 + wn + nt * 8 + 2 * tig;
            if (r0 < N_NODES) {
                __half2 v01 = __floats2half2_rn(c[mt][nt][0], c[mt][nt][1]);
                *reinterpret_cast<__half2*>(g_xph + (size_t)r0 * OUT_DIM + col) = v01;
            }
            if (r0 + 8 < N_NODES) {
                __half2 v23 = __floats2half2_rn(c[mt][nt][2], c[mt][nt][3]);
                *reinterpret_cast<__half2*>(g_xph + (size_t)(r0 + 8) * OUT_DIM + col) = v23;
            }
        }
    }

    // ---- epilogue 2: fused attention logits ----
    float psrc0[4], psrc1[4], pdst0[4], pdst1[4];
#pragma unroll
    for (int mt = 0; mt < 4; mt++) {
        psrc0[mt] = psrc1[mt] = pdst0[mt] = pdst1[mt] = 0.f;
#pragma unroll
        for (int nt = 0; nt < 4; nt++) {
            int col = n0 + wn + nt * 8 + 2 * tig;
            float as0 = att_src[col], as1 = att_src[col + 1];
            float ad0 = att_dst[col], ad1 = att_dst[col + 1];
            psrc0[mt] += c[mt][nt][0] * as0 + c[mt][nt][1] * as1;
            psrc1[mt] += c[mt][nt][2] * as0 + c[mt][nt][3] * as1;
            pdst0[mt] += c[mt][nt][0] * ad0 + c[mt][nt][1] * ad1;
            pdst1[mt] += c[mt][nt][2] * ad0 + c[mt][nt][3] * ad1;
        }
    }
#pragma unroll
    for (int off = 1; off <= 2; off <<= 1) {
#pragma unroll
        for (int mt = 0; mt < 4; mt++) {
            psrc0[mt] += __shfl_xor_sync(0xffffffffu, psrc0[mt], off);
            psrc1[mt] += __shfl_xor_sync(0xffffffffu, psrc1[mt], off);
            pdst0[mt] += __shfl_xor_sync(0xffffffffu, pdst0[mt], off);
            pdst1[mt] += __shfl_xor_sync(0xffffffffu, pdst1[mt], off);
        }
    }
    if (tig == 0) {
        int h = (n0 + wn) >> 6;
#pragma unroll
        for (int mt = 0; mt < 4; mt++) {
            int r0 = m0 + wm + mt * 16 + gID;
            if (r0 < N_NODES) {
                atomicAdd(&g_asrc[r0 * 4 + h], psrc0[mt]);
                atomicAdd(&g_adst[r0 * 4 + h], pdst0[mt]);
            }
            if (r0 + 8 < N_NODES) {
                atomicAdd(&g_asrc[(r0 + 8) * 4 + h], psrc1[mt]);
                atomicAdd(&g_adst[(r0 + 8) * 4 + h], pdst1[mt]);
            }
        }
    }
}

// ---------------- K3a: in-degree histogram ---------------------------------
__global__ __launch_bounds__(256) void hist_kernel(const void* __restrict__ ei)
{
    int i = blockIdx.x * blockDim.x + threadIdx.x;
    if (i >= E_TOT) return;
    int s, d;
    if (i < N_EDGES) load_edge(ei, i, s, d);
    else             d = i - N_EDGES;
    atomicAdd(&g_deg[d], 1);
}

// ---------------- K3b: coalesced 3-phase exclusive scan --------------------
__global__ __launch_bounds__(256) void scan1_kernel()
{
    __shared__ int sm[256];
    int tid = threadIdx.x;
    int i = blockIdx.x * 256 + tid;
    int v = (i < N_NODES) ? g_deg[i] : 0;
    sm[tid] = v;
    __syncthreads();
#pragma unroll
    for (int off = 1; off < 256; off <<= 1) {
        int t = (tid >= off) ? sm[tid - off] : 0;
        __syncthreads();
        sm[tid] += t;
        __syncthreads();
    }
    int incl = sm[tid];
    if (i < N_NODES) g_off[i] = incl - v;
    if (tid == 255) g_bsum[blockIdx.x] = incl;
}

__global__ __launch_bounds__(256) void scan2_kernel()
{
    __shared__ int sm[256];
    int tid = threadIdx.x;
    int v = (tid < NBLK_SCAN) ? g_bsum[tid] : 0;
    sm[tid] = v;
    __syncthreads();
#pragma unroll
    for (int off = 1; off < 256; off <<= 1) {
        int t = (tid >= off) ? sm[tid - off] : 0;
        __syncthreads();
        sm[tid] += t;
        __syncthreads();
    }
    if (tid < NBLK_SCAN) g_boff[tid] = sm[tid] - v;
}

__global__ __launch_bounds__(256) void scan3_kernel()
{
    int i = blockIdx.x * 256 + threadIdx.x;
    if (i < N_NODES) {
        int o = g_off[i] + g_boff[blockIdx.x];
        g_off[i] = o;
        g_cur[i] = o;
    }
}

// ---------------- K3c: scatter edges into CSR order + compute exp(logit) ---
__global__ __launch_bounds__(256) void scatter_kernel(const void* __restrict__ ei)
{
    int i = blockIdx.x * blockDim.x + threadIdx.x;
    if (i >= E_TOT) return;
    int s, d;
    if (i < N_EDGES) load_edge(ei, i, s, d);
    else             s = d = i - N_EDGES;   // self-loop

    float4 as = *reinterpret_cast<const float4*>(g_asrc + s * 4);
    float4 ad = *reinterpret_cast<const float4*>(g_adst + d * 4);
    float e0 = as.x + ad.x, e1 = as.y + ad.y, e2 = as.z + ad.z, e3 = as.w + ad.w;
    e0 = (e0 > 0.f) ? e0 : NEG_SLOPE * e0;
    e1 = (e1 > 0.f) ? e1 : NEG_SLOPE * e1;
    e2 = (e2 > 0.f) ? e2 : NEG_SLOPE * e2;
    e3 = (e3 > 0.f) ? e3 : NEG_SLOPE * e3;
    float4 ee = make_float4(__expf(e0), __expf(e1), __expf(e2), __expf(e3));

    int pos = atomicAdd(&g_cur[d], 1);
    g_csr_src[pos] = s;
    *reinterpret_cast<float4*>(g_csr_ee + (size_t)pos * 4) = ee;
}

// ---------------- K4: CSR aggregate (simple loop), fused softmax + ReLU ----
__global__ __launch_bounds__(256) void aggregate_csr_kernel(float* __restrict__ out)
{
    int d = (blockIdx.x * blockDim.x + threadIdx.x) >> 5;
    if (d >= N_NODES) return;
    int lane = threadIdx.x & 31;
    int h = lane >> 3;
    int beg = g_off[d];
    int end = g_cur[d];

    float a0 = 0.f, a1 = 0.f, a2 = 0.f, a3 = 0.f;
    float a4 = 0.f, a5 = 0.f, a6 = 0.f, a7 = 0.f;
    float denom = 0.f;

    for (int j = beg; j < end; j++) {
        int   s  = g_csr_src[j];
        float ee = g_csr_ee[(size_t)j * 4 + h];
        denom += ee;
        uint4 u = *reinterpret_cast<const uint4*>(
            g_xph + (size_t)s * OUT_DIM + lane * 8);
        const __half2* hp = reinterpret_cast<const __half2*>(&u);
        float2 f0 = __half22float2(hp[0]);
        float2 f1 = __half22float2(hp[1]);
        float2 f2 = __half22float2(hp[2]);
        float2 f3 = __half22float2(hp[3]);
        a0 += ee * f0.x; a1 += ee * f0.y;
        a2 += ee * f1.x; a3 += ee * f1.y;
        a4 += ee * f2.x; a5 += ee * f2.y;
        a6 += ee * f3.x; a7 += ee * f3.y;
    }

    float inv = 1.f / denom;
    float4 o0 = make_float4(fmaxf(a0 * inv, 0.f), fmaxf(a1 * inv, 0.f),
                            fmaxf(a2 * inv, 0.f), fmaxf(a3 * inv, 0.f));
    float4 o1 = make_float4(fmaxf(a4 * inv, 0.f), fmaxf(a5 * inv, 0.f),
                            fmaxf(a6 * inv, 0.f), fmaxf(a7 * inv, 0.f));
    float4* op = reinterpret_cast<float4*>(out + (size_t)d * OUT_DIM + lane * 8);
    op[0] = o0;
    op[1] = o1;
}

// ---------------- launch ----------------------------------------------------
extern "C" void kernel_launch(void* const* d_in, const int* in_sizes, int n_in,
                              void* d_out, int out_size)
{
    const float* x       = (const float*)d_in[0];
    const void*  ei      = d_in[1];
    const float* Wm      = (const float*)d_in[2];
    const float* att_src = (const float*)d_in[3];
    const float* att_dst = (const float*)d_in[4];
    float*       out     = (float*)d_out;

    static bool attr_set = false;
    if (!attr_set) {
        cudaFuncSetAttribute(gemm_tf32_kernel,
                             cudaFuncAttributeMaxDynamicSharedMemorySize, GEMM_SMEM);
        attr_set = true;
    }

    zero_kernel<<<NBLK_SCAN, 256>>>((const int*)ei);

    hist_kernel<<<(E_TOT + 255) / 256, 256>>>(ei);
    scan1_kernel<<<NBLK_SCAN, 256>>>();
    scan2_kernel<<<1, 256>>>();
    scan3_kernel<<<NBLK_SCAN, 256>>>();

    dim3 ggrid((N_NODES + GBM - 1) / GBM, OUT_DIM / GBN);
    gemm_tf32_kernel<<<ggrid, 256, GEMM_SMEM>>>(x, Wm, att_src, att_dst);

    scatter_kernel<<<(E_TOT + 255) / 256, 256>>>(ei);

    aggregate_csr_kernel<<<((size_t)N_NODES * 32 + 255) / 256, 256>>>(out);
}

// round 11
// speedup vs baseline: 2.3830x; 1.0651x over previous
#include <cuda_runtime.h>
#include <cuda_fp16.h>
#include <cstdint>

#define N_NODES 50000
#define N_EDGES 800000
#define E_TOT   (N_EDGES + N_NODES)
#define IN_DIM  256
#define OUT_DIM 256   // N_HEADS * HEAD_DIM
#define NEG_SLOPE 0.2f
#define NBLK_SCAN ((N_NODES + 255) / 256)   // 196

// ---------------- scratch (static device globals; no runtime allocation) ---
__device__ __align__(16) __half g_xph[(size_t)N_NODES * OUT_DIM]; // projected features, fp16 [N,256]
__device__ __align__(16) float g_asrc[N_NODES * 4];               // per-node src logits [N,4]
__device__ __align__(16) float g_adst[N_NODES * 4];               // per-node dst logits [N,4]
__device__ __align__(16) float g_csr_ee[(size_t)E_TOT * 4];       // exp(logit), CSR order [E+N,4]
__device__ int g_csr_src[E_TOT];                                  // src node id, CSR order
__device__ int g_deg[N_NODES];                                    // in-degree histogram
__device__ int g_off[N_NODES];                                    // CSR row start (block-LOCAL exclusive)
__device__ int g_cur[N_NODES];                                    // scatter cursor (block-LOCAL)
__device__ int g_bsum[NBLK_SCAN];                                 // per-block degree sums
__device__ int g_boff[NBLK_SCAN];                                 // scanned block offsets
__device__ int g_is64;                                            // edge_index dtype flag

// ---------------- helpers --------------------------------------------------
__device__ __forceinline__ uint32_t f2tf32(float f) {
    uint32_t r;
    asm("cvt.rna.tf32.f32 %0, %1;" : "=r"(r) : "f"(f));
    return r;
}

__device__ __forceinline__ void load_edge(const void* ei, int i, int& s, int& d) {
    if (g_is64) {
        const long long* p = (const long long*)ei;
        s = (int)p[i];
        d = (int)p[N_EDGES + i];
    } else {
        const int* p = (const int*)ei;
        s = p[i];
        d = p[N_EDGES + i];
    }
}

// ---------------- K0: zero degrees + logit accumulators + dtype detect -----
__global__ void zero_kernel(const int* __restrict__ ei32) {
    int i = blockIdx.x * blockDim.x + threadIdx.x;
    if (i < N_NODES) {
        g_deg[i] = 0;
        float4 z = make_float4(0.f, 0.f, 0.f, 0.f);
        *reinterpret_cast<float4*>(g_asrc + i * 4) = z;
        *reinterpret_cast<float4*>(g_adst + i * 4) = z;
    }
    if (blockIdx.x == 0 && threadIdx.x == 0) {
        int any = 0;
        for (int k = 0; k < 128; k++) any |= ei32[2 * k + 1];
        g_is64 = (any == 0) ? 1 : 0;
    }
}

// ---------------- K1: GEMM xp = x @ W (tf32 mma, cp.async 3-stage, ---------
//                      fused attention-logit epilogue)
#define GBM 128
#define GBN 128
#define GBK 32
#define NK_IT (IN_DIM / GBK)      // 8
#define A_LD 36                   // floats per A row (conflict-free frags)
#define B_LD 136                  // floats per B row (conflict-free frags)
#define A_STG_B (GBM * A_LD * 4)  // 18432 bytes per A stage
#define B_STG_B (GBK * B_LD * 4)  // 17408 bytes per B stage
#define B_BASE_B (3 * A_STG_B)    // 55296
#define GEMM_SMEM (3 * (A_STG_B + B_STG_B))  // 107520

__global__ __launch_bounds__(256) void gemm_tf32_kernel(
    const float* __restrict__ X, const float* __restrict__ Wm,
    const float* __restrict__ att_src, const float* __restrict__ att_dst)
{
    extern __shared__ char smem_raw[];
    float* Asf = reinterpret_cast<float*>(smem_raw);
    float* Bsf = reinterpret_cast<float*>(smem_raw + B_BASE_B);
    const uint32_t sbase = (uint32_t)__cvta_generic_to_shared(smem_raw);

    const int tid  = threadIdx.x;
    const int wid  = tid >> 5;
    const int lane = tid & 31;
    const int m0 = blockIdx.x * GBM;
    const int n0 = blockIdx.y * GBN;
    const int wm = (wid & 1) * 64;
    const int wn = (wid >> 1) * 32;
    const int gID = lane >> 2;
    const int tig = lane & 3;

#define ISSUE_STAGE(K0, STG) do {                                              \
        _Pragma("unroll")                                                      \
        for (int l = 0; l < 4; l++) {                                          \
            int idx = tid + l * 256;                                           \
            int row = idx >> 3, c4 = idx & 7;                                  \
            int gm = m0 + row;                                                 \
            int sz = (gm < N_NODES) ? 16 : 0;                                  \
            if (gm >= N_NODES) gm = N_NODES - 1;                               \
            uint32_t dst = sbase + (STG) * A_STG_B + row * (A_LD * 4) + c4 * 16;\
            const char* src = (const char*)X + (size_t)gm * (IN_DIM * 4)       \
                              + (K0) * 4 + c4 * 16;                            \
            asm volatile("cp.async.cg.shared.global [%0], [%1], 16, %2;"       \
                         :: "r"(dst), "l"(src), "r"(sz));                      \
        }                                                                      \
        _Pragma("unroll")                                                      \
        for (int l = 0; l < 4; l++) {                                          \
            int idx = tid + l * 256;                                           \
            int kr = idx >> 5, c4 = idx & 31;                                  \
            uint32_t dst = sbase + B_BASE_B + (STG) * B_STG_B                  \
                           + kr * (B_LD * 4) + c4 * 16;                        \
            const char* src = (const char*)Wm                                  \
                + ((size_t)((K0) + kr) * OUT_DIM + n0) * 4 + c4 * 16;          \
            asm volatile("cp.async.cg.shared.global [%0], [%1], 16;"           \
                         :: "r"(dst), "l"(src));                               \
        }                                                                      \
        asm volatile("cp.async.commit_group;" ::: "memory");                   \
    } while (0)

    float c[4][4][4];
#pragma unroll
    for (int i = 0; i < 4; i++)
#pragma unroll
        for (int j = 0; j < 4; j++)
#pragma unroll
            for (int r = 0; r < 4; r++) c[i][j][r] = 0.f;

    ISSUE_STAGE(0, 0);
    ISSUE_STAGE(GBK, 1);

    for (int it = 0; it < NK_IT; it++) {
        if (it == NK_IT - 1) asm volatile("cp.async.wait_group 0;" ::: "memory");
        else                 asm volatile("cp.async.wait_group 1;" ::: "memory");
        __syncthreads();

        const int stg = it % 3;
        const float* Af = Asf + stg * (GBM * A_LD);
        const float* Bf = Bsf + stg * (GBK * B_LD);

#pragma unroll
        for (int ks = 0; ks < 4; ks++) {
            const int kb = ks * 8;
            uint32_t a[4][4], b[4][2];
#pragma unroll
            for (int mt = 0; mt < 4; mt++) {
                int rb = wm + mt * 16;
                a[mt][0] = f2tf32(Af[(rb + gID    ) * A_LD + kb + tig    ]);
                a[mt][1] = f2tf32(Af[(rb + gID + 8) * A_LD + kb + tig    ]);
                a[mt][2] = f2tf32(Af[(rb + gID    ) * A_LD + kb + tig + 4]);
                a[mt][3] = f2tf32(Af[(rb + gID + 8) * A_LD + kb + tig + 4]);
            }
#pragma unroll
            for (int nt = 0; nt < 4; nt++) {
                int col = wn + nt * 8 + gID;
                b[nt][0] = f2tf32(Bf[(kb + tig    ) * B_LD + col]);
                b[nt][1] = f2tf32(Bf[(kb + tig + 4) * B_LD + col]);
            }
#pragma unroll
            for (int mt = 0; mt < 4; mt++)
#pragma unroll
                for (int nt = 0; nt < 4; nt++) {
                    asm volatile(
                        "mma.sync.aligned.m16n8k8.row.col.f32.tf32.tf32.f32 "
                        "{%0,%1,%2,%3}, {%4,%5,%6,%7}, {%8,%9}, {%0,%1,%2,%3};"
                        : "+f"(c[mt][nt][0]), "+f"(c[mt][nt][1]),
                          "+f"(c[mt][nt][2]), "+f"(c[mt][nt][3])
                        : "r"(a[mt][0]), "r"(a[mt][1]), "r"(a[mt][2]), "r"(a[mt][3]),
                          "r"(b[nt][0]), "r"(b[nt][1]));
                }
        }

        if (it + 2 < NK_IT) {
            ISSUE_STAGE((it + 2) * GBK, (it + 2) % 3);
        }
    }
#undef ISSUE_STAGE

    // ---- epilogue 1: fp16 xp stores ----
#pragma unroll
    for (int mt = 0; mt < 4; mt++) {
        int r0 = m0 + wm + mt * 16 + gID;
#pragma unroll
        for (int nt = 0; nt < 4; nt++) {
            int col = n0 + wn + nt * 8 + 2 * tig;
            if (r0 < N_NODES) {
                __half2 v01 = __floats2half2_rn(c[mt][nt][0], c[mt][nt][1]);
                *reinterpret_cast<__half2*>(g_xph + (size_t)r0 * OUT_DIM + col) = v01;
            }
            if (r0 + 8 < N_NODES) {
                __half2 v23 = __floats2half2_rn(c[mt][nt][2], c[mt][nt][3]);
                *reinterpret_cast<__half2*>(g_xph + (size_t)(r0 + 8) * OUT_DIM + col) = v23;
            }
        }
    }

    // ---- epilogue 2: fused attention logits ----
    float psrc0[4], psrc1[4], pdst0[4], pdst1[4];
#pragma unroll
    for (int mt = 0; mt < 4; mt++) {
        psrc0[mt] = psrc1[mt] = pdst0[mt] = pdst1[mt] = 0.f;
#pragma unroll
        for (int nt = 0; nt < 4; nt++) {
            int col = n0 + wn + nt * 8 + 2 * tig;
            float as0 = att_src[col], as1 = att_src[col + 1];
            float ad0 = att_dst[col], ad1 = att_dst[col + 1];
            psrc0[mt] += c[mt][nt][0] * as0 + c[mt][nt][1] * as1;
            psrc1[mt] += c[mt][nt][2] * as0 + c[mt][nt][3] * as1;
            pdst0[mt] += c[mt][nt][0] * ad0 + c[mt][nt][1] * ad1;
            pdst1[mt] += c[mt][nt][2] * ad0 + c[mt][nt][3] * ad1;
        }
    }
#pragma unroll
    for (int off = 1; off <= 2; off <<= 1) {
#pragma unroll
        for (int mt = 0; mt < 4; mt++) {
            psrc0[mt] += __shfl_xor_sync(0xffffffffu, psrc0[mt], off);
            psrc1[mt] += __shfl_xor_sync(0xffffffffu, psrc1[mt], off);
            pdst0[mt] += __shfl_xor_sync(0xffffffffu, pdst0[mt], off);
            pdst1[mt] += __shfl_xor_sync(0xffffffffu, pdst1[mt], off);
        }
    }
    if (tig == 0) {
        int h = (n0 + wn) >> 6;
#pragma unroll
        for (int mt = 0; mt < 4; mt++) {
            int r0 = m0 + wm + mt * 16 + gID;
            if (r0 < N_NODES) {
                atomicAdd(&g_asrc[r0 * 4 + h], psrc0[mt]);
                atomicAdd(&g_adst[r0 * 4 + h], pdst0[mt]);
            }
            if (r0 + 8 < N_NODES) {
                atomicAdd(&g_asrc[(r0 + 8) * 4 + h], psrc1[mt]);
                atomicAdd(&g_adst[(r0 + 8) * 4 + h], pdst1[mt]);
            }
        }
    }
}

// ---------------- K3a: in-degree histogram ---------------------------------
__global__ __launch_bounds__(256) void hist_kernel(const void* __restrict__ ei)
{
    int i = blockIdx.x * blockDim.x + threadIdx.x;
    if (i >= E_TOT) return;
    int s, d;
    if (i < N_EDGES) load_edge(ei, i, s, d);
    else             d = i - N_EDGES;
    atomicAdd(&g_deg[d], 1);
}

// ---------------- K3b: 2-phase exclusive scan (block-local + block sums) ---
__global__ __launch_bounds__(256) void scan1_kernel()
{
    __shared__ int sm[256];
    int tid = threadIdx.x;
    int i = blockIdx.x * 256 + tid;
    int v = (i < N_NODES) ? g_deg[i] : 0;
    sm[tid] = v;
    __syncthreads();
#pragma unroll
    for (int off = 1; off < 256; off <<= 1) {
        int t = (tid >= off) ? sm[tid - off] : 0;
        __syncthreads();
        sm[tid] += t;
        __syncthreads();
    }
    int incl = sm[tid];
    if (i < N_NODES) {
        int excl = incl - v;
        g_off[i] = excl;          // block-LOCAL exclusive offset
        g_cur[i] = excl;          // block-LOCAL cursor
    }
    if (tid == 255) g_bsum[blockIdx.x] = incl;
}

__global__ __launch_bounds__(256) void scan2_kernel()
{
    __shared__ int sm[256];
    int tid = threadIdx.x;
    int v = (tid < NBLK_SCAN) ? g_bsum[tid] : 0;
    sm[tid] = v;
    __syncthreads();
#pragma unroll
    for (int off = 1; off < 256; off <<= 1) {
        int t = (tid >= off) ? sm[tid - off] : 0;
        __syncthreads();
        sm[tid] += t;
        __syncthreads();
    }
    if (tid < NBLK_SCAN) g_boff[tid] = sm[tid] - v;
}

// ---------------- K3c: scatter edges into CSR order + compute exp(logit) ---
__global__ __launch_bounds__(256) void scatter_kernel(const void* __restrict__ ei)
{
    int i = blockIdx.x * blockDim.x + threadIdx.x;
    if (i >= E_TOT) return;
    int s, d;
    if (i < N_EDGES) load_edge(ei, i, s, d);
    else             s = d = i - N_EDGES;   // self-loop

    float4 as = *reinterpret_cast<const float4*>(g_asrc + s * 4);
    float4 ad = *reinterpret_cast<const float4*>(g_adst + d * 4);
    float e0 = as.x + ad.x, e1 = as.y + ad.y, e2 = as.z + ad.z, e3 = as.w + ad.w;
    e0 = (e0 > 0.f) ? e0 : NEG_SLOPE * e0;
    e1 = (e1 > 0.f) ? e1 : NEG_SLOPE * e1;
    e2 = (e2 > 0.f) ? e2 : NEG_SLOPE * e2;
    e3 = (e3 > 0.f) ? e3 : NEG_SLOPE * e3;
    float4 ee = make_float4(__expf(e0), __expf(e1), __expf(e2), __expf(e3));

    int pos = atomicAdd(&g_cur[d], 1) + g_boff[d >> 8];
    g_csr_src[pos] = s;
    *reinterpret_cast<float4*>(g_csr_ee + (size_t)pos * 4) = ee;
}

// ---------------- K4: CSR aggregate (simple loop), fused softmax + ReLU ----
__global__ __launch_bounds__(256) void aggregate_csr_kernel(float* __restrict__ out)
{
    int d = (blockIdx.x * blockDim.x + threadIdx.x) >> 5;
    if (d >= N_NODES) return;
    int lane = threadIdx.x & 31;
    int h = lane >> 3;
    int boff = g_boff[d >> 8];
    int beg = g_off[d] + boff;
    int end = g_cur[d] + boff;

    float a0 = 0.f, a1 = 0.f, a2 = 0.f, a3 = 0.f;
    float a4 = 0.f, a5 = 0.f, a6 = 0.f, a7 = 0.f;
    float denom = 0.f;

    for (int j = beg; j < end; j++) {
        int   s  = g_csr_src[j];
        float ee = g_csr_ee[(size_t)j * 4 + h];
        denom += ee;
        uint4 u = *reinterpret_cast<const uint4*>(
            g_xph + (size_t)s * OUT_DIM + lane * 8);
        const __half2* hp = reinterpret_cast<const __half2*>(&u);
        float2 f0 = __half22float2(hp[0]);
        float2 f1 = __half22float2(hp[1]);
        float2 f2 = __half22float2(hp[2]);
        float2 f3 = __half22float2(hp[3]);
        a0 += ee * f0.x; a1 += ee * f0.y;
        a2 += ee * f1.x; a3 += ee * f1.y;
        a4 += ee * f2.x; a5 += ee * f2.y;
        a6 += ee * f3.x; a7 += ee * f3.y;
    }

    float inv = 1.f / denom;
    float4 o0 = make_float4(fmaxf(a0 * inv, 0.f), fmaxf(a1 * inv, 0.f),
                            fmaxf(a2 * inv, 0.f), fmaxf(a3 * inv, 0.f));
    float4 o1 = make_float4(fmaxf(a4 * inv, 0.f), fmaxf(a5 * inv, 0.f),
                            fmaxf(a6 * inv, 0.f), fmaxf(a7 * inv, 0.f));
    float4* op = reinterpret_cast<float4*>(out + (size_t)d * OUT_DIM + lane * 8);
    op[0] = o0;
    op[1] = o1;
}

// ---------------- launch ----------------------------------------------------
extern "C" void kernel_launch(void* const* d_in, const int* in_sizes, int n_in,
                              void* d_out, int out_size)
{
    const float* x       = (const float*)d_in[0];
    const void*  ei      = d_in[1];
    const float* Wm      = (const float*)d_in[2];
    const float* att_src = (const float*)d_in[3];
    const float* att_dst = (const float*)d_in[4];
    float*       out     = (float*)d_out;

    static cudaStream_t s1 = nullptr;
    static cudaEvent_t evFork = nullptr, evJoin = nullptr;
    if (!s1) {
        cudaStreamCreateWithFlags(&s1, cudaStreamNonBlocking);
        cudaEventCreateWithFlags(&evFork, cudaEventDisableTiming);
        cudaEventCreateWithFlags(&evJoin, cudaEventDisableTiming);
        cudaFuncSetAttribute(gemm_tf32_kernel,
                             cudaFuncAttributeMaxDynamicSharedMemorySize, GEMM_SMEM);
    }

    // zeroing (deg + logit accumulators) gates BOTH branches
    zero_kernel<<<NBLK_SCAN, 256>>>((const int*)ei);
    cudaEventRecord(evFork, 0);
    cudaStreamWaitEvent(s1, evFork, 0);

    // branch B (side stream): edge-prep chain, independent of GEMM
    hist_kernel<<<(E_TOT + 255) / 256, 256, 0, s1>>>(ei);
    scan1_kernel<<<NBLK_SCAN, 256, 0, s1>>>();
    scan2_kernel<<<1, 256, 0, s1>>>();
    cudaEventRecord(evJoin, s1);

    // branch A (main stream): GEMM + fused logits, runs concurrently
    dim3 ggrid((N_NODES + GBM - 1) / GBM, OUT_DIM / GBN);
    gemm_tf32_kernel<<<ggrid, 256, GEMM_SMEM>>>(x, Wm, att_src, att_dst);

    // join: scatter needs logits (A) + cursors (B)
    cudaStreamWaitEvent(0, evJoin, 0);
    scatter_kernel<<<(E_TOT + 255) / 256, 256>>>(ei);

    aggregate_csr_kernel<<<((size_t)N_NODES * 32 + 255) / 256, 256>>>(out);
}

// round 12
// speedup vs baseline: 2.4204x; 1.0157x over previous
#include <cuda_runtime.h>
#include <cuda_fp16.h>
#include <cstdint>

#define N_NODES 50000
#define N_EDGES 800000
#define E_TOT   (N_EDGES + N_NODES)
#define IN_DIM  256
#define OUT_DIM 256   // N_HEADS * HEAD_DIM
#define NEG_SLOPE 0.2f
#define NBLK_SCAN ((N_NODES + 255) / 256)   // 196

// ---------------- scratch (static device globals; no runtime allocation) ---
__device__ __align__(16) __half g_xph[(size_t)N_NODES * OUT_DIM]; // projected features, fp16 [N,256]
__device__ __align__(16) float g_asrc[N_NODES * 4];               // per-node src logits [N,4]
__device__ __align__(16) float g_adst[N_NODES * 4];               // per-node dst logits [N,4]
__device__ __align__(16) float g_csr_ee[(size_t)E_TOT * 4];       // exp(logit), CSR order [E+N,4]
__device__ int g_csr_src[E_TOT];                                  // src node id, CSR order
__device__ int g_deg[N_NODES];                                    // in-degree histogram
__device__ int g_off[N_NODES];                                    // CSR row start (block-LOCAL exclusive)
__device__ int g_cur[N_NODES];                                    // scatter cursor (block-LOCAL)
__device__ int g_bsum[NBLK_SCAN];                                 // per-block degree sums
__device__ int g_boff[NBLK_SCAN];                                 // scanned block offsets
__device__ int g_scan_ctr;                                        // last-block ticket
__device__ int g_is64;                                            // edge_index dtype flag

// ---------------- helpers --------------------------------------------------
__device__ __forceinline__ uint32_t f2tf32(float f) {
    uint32_t r;
    asm("cvt.rna.tf32.f32 %0, %1;" : "=r"(r) : "f"(f));
    return r;
}

__device__ __forceinline__ void load_edge(const void* ei, int i, int& s, int& d) {
    if (g_is64) {
        const long long* p = (const long long*)ei;
        s = (int)p[i];
        d = (int)p[N_EDGES + i];
    } else {
        const int* p = (const int*)ei;
        s = p[i];
        d = p[N_EDGES + i];
    }
}

// ---------------- K0a: zero logit accumulators + dtype detect (main) -------
__global__ void zero_logit_kernel(const int* __restrict__ ei32) {
    int i = blockIdx.x * blockDim.x + threadIdx.x;
    if (i < N_NODES) {
        float4 z = make_float4(0.f, 0.f, 0.f, 0.f);
        *reinterpret_cast<float4*>(g_asrc + i * 4) = z;
        *reinterpret_cast<float4*>(g_adst + i * 4) = z;
    }
    if (blockIdx.x == 0 && threadIdx.x == 0) {
        int any = 0;
        for (int k = 0; k < 128; k++) any |= ei32[2 * k + 1];
        g_is64 = (any == 0) ? 1 : 0;
    }
}

// ---------------- K0b: zero degrees + scan ticket (side stream) ------------
__global__ void zero_deg_kernel() {
    int i = blockIdx.x * blockDim.x + threadIdx.x;
    if (i < N_NODES) g_deg[i] = 0;
    if (blockIdx.x == 0 && threadIdx.x == 0) g_scan_ctr = 0;
}

// ---------------- K1: GEMM xp = x @ W (tf32 mma, cp.async 3-stage, ---------
//                      fused attention-logit epilogue)
#define GBM 128
#define GBN 128
#define GBK 32
#define NK_IT (IN_DIM / GBK)      // 8
#define A_LD 36
#define B_LD 136
#define A_STG_B (GBM * A_LD * 4)
#define B_STG_B (GBK * B_LD * 4)
#define B_BASE_B (3 * A_STG_B)
#define GEMM_SMEM (3 * (A_STG_B + B_STG_B))  // 107520

__global__ __launch_bounds__(256) void gemm_tf32_kernel(
    const float* __restrict__ X, const float* __restrict__ Wm,
    const float* __restrict__ att_src, const float* __restrict__ att_dst)
{
    extern __shared__ char smem_raw[];
    float* Asf = reinterpret_cast<float*>(smem_raw);
    float* Bsf = reinterpret_cast<float*>(smem_raw + B_BASE_B);
    const uint32_t sbase = (uint32_t)__cvta_generic_to_shared(smem_raw);

    const int tid  = threadIdx.x;
    const int wid  = tid >> 5;
    const int lane = tid & 31;
    const int m0 = blockIdx.x * GBM;
    const int n0 = blockIdx.y * GBN;
    const int wm = (wid & 1) * 64;
    const int wn = (wid >> 1) * 32;
    const int gID = lane >> 2;
    const int tig = lane & 3;

#define ISSUE_STAGE(K0, STG) do {                                              \
        _Pragma("unroll")                                                      \
        for (int l = 0; l < 4; l++) {                                          \
            int idx = tid + l * 256;                                           \
            int row = idx >> 3, c4 = idx & 7;                                  \
            int gm = m0 + row;                                                 \
            int sz = (gm < N_NODES) ? 16 : 0;                                  \
            if (gm >= N_NODES) gm = N_NODES - 1;                               \
            uint32_t dst = sbase + (STG) * A_STG_B + row * (A_LD * 4) + c4 * 16;\
            const char* src = (const char*)X + (size_t)gm * (IN_DIM * 4)       \
                              + (K0) * 4 + c4 * 16;                            \
            asm volatile("cp.async.cg.shared.global [%0], [%1], 16, %2;"       \
                         :: "r"(dst), "l"(src), "r"(sz));                      \
        }                                                                      \
        _Pragma("unroll")                                                      \
        for (int l = 0; l < 4; l++) {                                          \
            int idx = tid + l * 256;                                           \
            int kr = idx >> 5, c4 = idx & 31;                                  \
            uint32_t dst = sbase + B_BASE_B + (STG) * B_STG_B                  \
                           + kr * (B_LD * 4) + c4 * 16;                        \
            const char* src = (const char*)Wm                                  \
                + ((size_t)((K0) + kr) * OUT_DIM + n0) * 4 + c4 * 16;          \
            asm volatile("cp.async.cg.shared.global [%0], [%1], 16;"           \
                         :: "r"(dst), "l"(src));                               \
        }                                                                      \
        asm volatile("cp.async.commit_group;" ::: "memory");                   \
    } while (0)

    float c[4][4][4];
#pragma unroll
    for (int i = 0; i < 4; i++)
#pragma unroll
        for (int j = 0; j < 4; j++)
#pragma unroll
            for (int r = 0; r < 4; r++) c[i][j][r] = 0.f;

    ISSUE_STAGE(0, 0);
    ISSUE_STAGE(GBK, 1);

    for (int it = 0; it < NK_IT; it++) {
        if (it == NK_IT - 1) asm volatile("cp.async.wait_group 0;" ::: "memory");
        else                 asm volatile("cp.async.wait_group 1;" ::: "memory");
        __syncthreads();

        const int stg = it % 3;
        const float* Af = Asf + stg * (GBM * A_LD);
        const float* Bf = Bsf + stg * (GBK * B_LD);

#pragma unroll
        for (int ks = 0; ks < 4; ks++) {
            const int kb = ks * 8;
            uint32_t a[4][4], b[4][2];
#pragma unroll
            for (int mt = 0; mt < 4; mt++) {
                int rb = wm + mt * 16;
                a[mt][0] = f2tf32(Af[(rb + gID    ) * A_LD + kb + tig    ]);
                a[mt][1] = f2tf32(Af[(rb + gID + 8) * A_LD + kb + tig    ]);
                a[mt][2] = f2tf32(Af[(rb + gID    ) * A_LD + kb + tig + 4]);
                a[mt][3] = f2tf32(Af[(rb + gID + 8) * A_LD + kb + tig + 4]);
            }
#pragma unroll
            for (int nt = 0; nt < 4; nt++) {
                int col = wn + nt * 8 + gID;
                b[nt][0] = f2tf32(Bf[(kb + tig    ) * B_LD + col]);
                b[nt][1] = f2tf32(Bf[(kb + tig + 4) * B_LD + col]);
            }
#pragma unroll
            for (int mt = 0; mt < 4; mt++)
#pragma unroll
                for (int nt = 0; nt < 4; nt++) {
                    asm volatile(
                        "mma.sync.aligned.m16n8k8.row.col.f32.tf32.tf32.f32 "
                        "{%0,%1,%2,%3}, {%4,%5,%6,%7}, {%8,%9}, {%0,%1,%2,%3};"
                        : "+f"(c[mt][nt][0]), "+f"(c[mt][nt][1]),
                          "+f"(c[mt][nt][2]), "+f"(c[mt][nt][3])
                        : "r"(a[mt][0]), "r"(a[mt][1]), "r"(a[mt][2]), "r"(a[mt][3]),
                          "r"(b[nt][0]), "r"(b[nt][1]));
                }
        }

        if (it + 2 < NK_IT) {
            ISSUE_STAGE((it + 2) * GBK, (it + 2) % 3);
        }
    }
#undef ISSUE_STAGE

    // ---- epilogue 1: fp16 xp stores ----
#pragma unroll
    for (int mt = 0; mt < 4; mt++) {
        int r0 = m0 + wm + mt * 16 + gID;
#pragma unroll
        for (int nt = 0; nt < 4; nt++) {
            int col = n0 + wn + nt * 8 + 2 * tig;
            if (r0 < N_NODES) {
                __half2 v01 = __floats2half2_rn(c[mt][nt][0], c[mt][nt][1]);
                *reinterpret_cast<__half2*>(g_xph + (size_t)r0 * OUT_DIM + col) = v01;
            }
            if (r0 + 8 < N_NODES) {
                __half2 v23 = __floats2half2_rn(c[mt][nt][2], c[mt][nt][3]);
                *reinterpret_cast<__half2*>(g_xph + (size_t)(r0 + 8) * OUT_DIM + col) = v23;
            }
        }
    }

    // ---- epilogue 2: fused attention logits ----
    float psrc0[4], psrc1[4], pdst0[4], pdst1[4];
#pragma unroll
    for (int mt = 0; mt < 4; mt++) {
        psrc0[mt] = psrc1[mt] = pdst0[mt] = pdst1[mt] = 0.f;
#pragma unroll
        for (int nt = 0; nt < 4; nt++) {
            int col = n0 + wn + nt * 8 + 2 * tig;
            float as0 = att_src[col], as1 = att_src[col + 1];
            float ad0 = att_dst[col], ad1 = att_dst[col + 1];
            psrc0[mt] += c[mt][nt][0] * as0 + c[mt][nt][1] * as1;
            psrc1[mt] += c[mt][nt][2] * as0 + c[mt][nt][3] * as1;
            pdst0[mt] += c[mt][nt][0] * ad0 + c[mt][nt][1] * ad1;
            pdst1[mt] += c[mt][nt][2] * ad0 + c[mt][nt][3] * ad1;
        }
    }
#pragma unroll
    for (int off = 1; off <= 2; off <<= 1) {
#pragma unroll
        for (int mt = 0; mt < 4; mt++) {
            psrc0[mt] += __shfl_xor_sync(0xffffffffu, psrc0[mt], off);
            psrc1[mt] += __shfl_xor_sync(0xffffffffu, psrc1[mt], off);
            pdst0[mt] += __shfl_xor_sync(0xffffffffu, pdst0[mt], off);
            pdst1[mt] += __shfl_xor_sync(0xffffffffu, pdst1[mt], off);
        }
    }
    if (tig == 0) {
        int h = (n0 + wn) >> 6;
#pragma unroll
        for (int mt = 0; mt < 4; mt++) {
            int r0 = m0 + wm + mt * 16 + gID;
            if (r0 < N_NODES) {
                atomicAdd(&g_asrc[r0 * 4 + h], psrc0[mt]);
                atomicAdd(&g_adst[r0 * 4 + h], pdst0[mt]);
            }
            if (r0 + 8 < N_NODES) {
                atomicAdd(&g_asrc[(r0 + 8) * 4 + h], psrc1[mt]);
                atomicAdd(&g_adst[(r0 + 8) * 4 + h], pdst1[mt]);
            }
        }
    }
}

// ---------------- K3a: in-degree histogram ---------------------------------
__global__ __launch_bounds__(256) void hist_kernel(const void* __restrict__ ei)
{
    int i = blockIdx.x * blockDim.x + threadIdx.x;
    if (i >= E_TOT) return;
    int s, d;
    if (i < N_EDGES) load_edge(ei, i, s, d);
    else             d = i - N_EDGES;
    atomicAdd(&g_deg[d], 1);
}

// ---------------- K3b: fused exclusive scan (last-block-done pattern) ------
__global__ __launch_bounds__(256) void scan_fused_kernel()
{
    __shared__ int sm[256];
    __shared__ bool isLast;
    int tid = threadIdx.x;
    int i = blockIdx.x * 256 + tid;
    int v = (i < N_NODES) ? g_deg[i] : 0;
    sm[tid] = v;
    __syncthreads();
#pragma unroll
    for (int off = 1; off < 256; off <<= 1) {
        int t = (tid >= off) ? sm[tid - off] : 0;
        __syncthreads();
        sm[tid] += t;
        __syncthreads();
    }
    int incl = sm[tid];
    if (i < N_NODES) {
        int excl = incl - v;
        g_off[i] = excl;          // block-LOCAL exclusive
        g_cur[i] = excl;
    }
    if (tid == 255) g_bsum[blockIdx.x] = incl;

    // last finished block scans the block sums
    __threadfence();
    if (tid == 0) {
        int ticket = atomicAdd(&g_scan_ctr, 1);
        isLast = (ticket == gridDim.x - 1);
    }
    __syncthreads();
    if (isLast) {
        int bv = (tid < NBLK_SCAN) ? g_bsum[tid] : 0;
        sm[tid] = bv;
        __syncthreads();
#pragma unroll
        for (int off = 1; off < 256; off <<= 1) {
            int t = (tid >= off) ? sm[tid - off] : 0;
            __syncthreads();
            sm[tid] += t;
            __syncthreads();
        }
        if (tid < NBLK_SCAN) g_boff[tid] = sm[tid] - bv;
    }
}

// ---------------- K3c: scatter edges into CSR order + compute exp(logit) ---
__global__ __launch_bounds__(256) void scatter_kernel(const void* __restrict__ ei)
{
    int i = blockIdx.x * blockDim.x + threadIdx.x;
    if (i >= E_TOT) return;
    int s, d;
    if (i < N_EDGES) load_edge(ei, i, s, d);
    else             s = d = i - N_EDGES;   // self-loop

    float4 as = *reinterpret_cast<const float4*>(g_asrc + s * 4);
    float4 ad = *reinterpret_cast<const float4*>(g_adst + d * 4);
    float e0 = as.x + ad.x, e1 = as.y + ad.y, e2 = as.z + ad.z, e3 = as.w + ad.w;
    e0 = (e0 > 0.f) ? e0 : NEG_SLOPE * e0;
    e1 = (e1 > 0.f) ? e1 : NEG_SLOPE * e1;
    e2 = (e2 > 0.f) ? e2 : NEG_SLOPE * e2;
    e3 = (e3 > 0.f) ? e3 : NEG_SLOPE * e3;
    float4 ee = make_float4(__expf(e0), __expf(e1), __expf(e2), __expf(e3));

    int pos = atomicAdd(&g_cur[d], 1) + g_boff[d >> 8];
    g_csr_src[pos] = s;
    *reinterpret_cast<float4*>(g_csr_ee + (size_t)pos * 4) = ee;
}

// ---------------- K4: CSR aggregate (simple loop), fused softmax + ReLU ----
__global__ __launch_bounds__(256) void aggregate_csr_kernel(float* __restrict__ out)
{
    int d = (blockIdx.x * blockDim.x + threadIdx.x) >> 5;
    if (d >= N_NODES) return;
    int lane = threadIdx.x & 31;
    int h = lane >> 3;
    int boff = g_boff[d >> 8];
    int beg = g_off[d] + boff;
    int end = g_cur[d] + boff;

    float a0 = 0.f, a1 = 0.f, a2 = 0.f, a3 = 0.f;
    float a4 = 0.f, a5 = 0.f, a6 = 0.f, a7 = 0.f;
    float denom = 0.f;

    for (int j = beg; j < end; j++) {
        int   s  = __ldg(g_csr_src + j);
        float ee = __ldg(g_csr_ee + (size_t)j * 4 + h);
        denom += ee;
        uint4 u = __ldg(reinterpret_cast<const uint4*>(
            g_xph + (size_t)s * OUT_DIM + lane * 8));
        const __half2* hp = reinterpret_cast<const __half2*>(&u);
        float2 f0 = __half22float2(hp[0]);
        float2 f1 = __half22float2(hp[1]);
        float2 f2 = __half22float2(hp[2]);
        float2 f3 = __half22float2(hp[3]);
        a0 += ee * f0.x; a1 += ee * f0.y;
        a2 += ee * f1.x; a3 += ee * f1.y;
        a4 += ee * f2.x; a5 += ee * f2.y;
        a6 += ee * f3.x; a7 += ee * f3.y;
    }

    float inv = 1.f / denom;
    float4 o0 = make_float4(fmaxf(a0 * inv, 0.f), fmaxf(a1 * inv, 0.f),
                            fmaxf(a2 * inv, 0.f), fmaxf(a3 * inv, 0.f));
    float4 o1 = make_float4(fmaxf(a4 * inv, 0.f), fmaxf(a5 * inv, 0.f),
                            fmaxf(a6 * inv, 0.f), fmaxf(a7 * inv, 0.f));
    float4* op = reinterpret_cast<float4*>(out + (size_t)d * OUT_DIM + lane * 8);
    __stcs(op, o0);       // streaming store: out never re-read; keep L2 for xp
    __stcs(op + 1, o1);
}

// ---------------- launch ----------------------------------------------------
extern "C" void kernel_launch(void* const* d_in, const int* in_sizes, int n_in,
                              void* d_out, int out_size)
{
    const float* x       = (const float*)d_in[0];
    const void*  ei      = d_in[1];
    const float* Wm      = (const float*)d_in[2];
    const float* att_src = (const float*)d_in[3];
    const float* att_dst = (const float*)d_in[4];
    float*       out     = (float*)d_out;

    static cudaStream_t s1 = nullptr;
    static cudaEvent_t evFork = nullptr, evJoin = nullptr;
    if (!s1) {
        cudaStreamCreateWithFlags(&s1, cudaStreamNonBlocking);
        cudaEventCreateWithFlags(&evFork, cudaEventDisableTiming);
        cudaEventCreateWithFlags(&evJoin, cudaEventDisableTiming);
        cudaFuncSetAttribute(gemm_tf32_kernel,
                             cudaFuncAttributeMaxDynamicSharedMemorySize, GEMM_SMEM);
    }

    // fork at the very top: both branches start immediately
    cudaEventRecord(evFork, 0);
    cudaStreamWaitEvent(s1, evFork, 0);

    // branch B (side stream): deg-zero -> hist -> fused scan
    zero_deg_kernel<<<NBLK_SCAN, 256, 0, s1>>>();
    hist_kernel<<<(E_TOT + 255) / 256, 256, 0, s1>>>(ei);
    scan_fused_kernel<<<NBLK_SCAN, 256, 0, s1>>>();
    cudaEventRecord(evJoin, s1);

    // branch A (main stream): logit-zero -> GEMM + fused logits
    zero_logit_kernel<<<NBLK_SCAN, 256>>>((const int*)ei);
    dim3 ggrid((N_NODES + GBM - 1) / GBM, OUT_DIM / GBN);
    gemm_tf32_kernel<<<ggrid, 256, GEMM_SMEM>>>(x, Wm, att_src, att_dst);

    // join: scatter needs logits (A) + cursors (B)
    cudaStreamWaitEvent(0, evJoin, 0);
    scatter_kernel<<<(E_TOT + 255) / 256, 256>>>(ei);

    aggregate_csr_kernel<<<((size_t)N_NODES * 32 + 255) / 256, 256>>>(out);
}

// round 13
// speedup vs baseline: 2.4534x; 1.0137x over previous
#include <cuda_runtime.h>
#include <cuda_fp16.h>
#include <cstdint>

#define N_NODES 50000
#define N_EDGES 800000
#define E_TOT   (N_EDGES + N_NODES)
#define IN_DIM  256
#define OUT_DIM 256   // N_HEADS * HEAD_DIM
#define NEG_SLOPE 0.2f
#define NBLK_SCAN ((N_NODES + 255) / 256)   // 196

// ---------------- scratch (static device globals; no runtime allocation) ---
__device__ __align__(16) __half g_xph[(size_t)N_NODES * OUT_DIM]; // projected features, fp16 [N,256]
__device__ __align__(16) float g_asrc[N_NODES * 4];               // per-node src logits [N,4]
__device__ __align__(16) float g_adst[N_NODES * 4];               // per-node dst logits [N,4]
__device__ __align__(16) float g_csr_ee[(size_t)E_TOT * 4];       // exp(logit), CSR order [E+N,4]
__device__ int g_csr_src[E_TOT];                                  // src node id, CSR order
__device__ int g_deg[N_NODES];                                    // in-degree histogram
__device__ int g_off[N_NODES];                                    // CSR row start (block-LOCAL exclusive)
__device__ int g_cur[N_NODES];                                    // scatter cursor (block-LOCAL)
__device__ int g_bsum[NBLK_SCAN];                                 // per-block degree sums
__device__ int g_boff[NBLK_SCAN];                                 // scanned block offsets
__device__ int g_scan_ctr;                                        // last-block ticket
__device__ int g_is64;                                            // edge_index dtype flag

// ---------------- helpers --------------------------------------------------
__device__ __forceinline__ uint32_t f2tf32(float f) {
    uint32_t r;
    asm("cvt.rna.tf32.f32 %0, %1;" : "=r"(r) : "f"(f));
    return r;
}

__device__ __forceinline__ void load_edge(const void* ei, int i, int& s, int& d) {
    if (g_is64) {
        const long long* p = (const long long*)ei;
        s = (int)p[i];
        d = (int)p[N_EDGES + i];
    } else {
        const int* p = (const int*)ei;
        s = p[i];
        d = p[N_EDGES + i];
    }
}

// ---------------- K0a: zero logit accumulators + parallel dtype detect -----
__global__ void zero_logit_kernel(const int* __restrict__ ei32) {
    __shared__ int s_any[128];
    int i = blockIdx.x * blockDim.x + threadIdx.x;
    if (i < N_NODES) {
        float4 z = make_float4(0.f, 0.f, 0.f, 0.f);
        *reinterpret_cast<float4*>(g_asrc + i * 4) = z;
        *reinterpret_cast<float4*>(g_adst + i * 4) = z;
    }
    if (blockIdx.x == 0) {
        int t = threadIdx.x;
        if (t < 128) s_any[t] = ei32[2 * t + 1];   // parallel probe of odd words
        __syncthreads();
        if (t < 64) s_any[t] |= s_any[t + 64];
        __syncthreads();
        if (t < 32) {
            int v = s_any[t] | s_any[t + 32];
#pragma unroll
            for (int off = 16; off > 0; off >>= 1)
                v |= __shfl_down_sync(0xffffffffu, v, off);
            if (t == 0) g_is64 = (v == 0) ? 1 : 0;
        }
    }
}

// ---------------- K0b: zero degrees + scan ticket (side stream) ------------
__global__ void zero_deg_kernel() {
    int i = blockIdx.x * blockDim.x + threadIdx.x;
    if (i < N_NODES) g_deg[i] = 0;
    if (blockIdx.x == 0 && threadIdx.x == 0) g_scan_ctr = 0;
}

// ---------------- K1: GEMM xp = x @ W (tf32 mma, cp.async 3-stage, ---------
//                      fused attention-logit epilogue, 2 CTAs/SM)
#define GBM 128
#define GBN 128
#define GBK 32
#define NK_IT (IN_DIM / GBK)      // 8
#define A_LD 36
#define B_LD 136
#define A_STG_B (GBM * A_LD * 4)
#define B_STG_B (GBK * B_LD * 4)
#define B_BASE_B (3 * A_STG_B)
#define GEMM_SMEM (3 * (A_STG_B + B_STG_B))  // 107520

__global__ __launch_bounds__(256, 2) void gemm_tf32_kernel(
    const float* __restrict__ X, const float* __restrict__ Wm,
    const float* __restrict__ att_src, const float* __restrict__ att_dst)
{
    extern __shared__ char smem_raw[];
    float* Asf = reinterpret_cast<float*>(smem_raw);
    float* Bsf = reinterpret_cast<float*>(smem_raw + B_BASE_B);
    const uint32_t sbase = (uint32_t)__cvta_generic_to_shared(smem_raw);

    const int tid  = threadIdx.x;
    const int wid  = tid >> 5;
    const int lane = tid & 31;
    const int m0 = blockIdx.x * GBM;
    const int n0 = blockIdx.y * GBN;
    const int wm = (wid & 1) * 64;
    const int wn = (wid >> 1) * 32;
    const int gID = lane >> 2;
    const int tig = lane & 3;

#define ISSUE_STAGE(K0, STG) do {                                              \
        _Pragma("unroll")                                                      \
        for (int l = 0; l < 4; l++) {                                          \
            int idx = tid + l * 256;                                           \
            int row = idx >> 3, c4 = idx & 7;                                  \
            int gm = m0 + row;                                                 \
            int sz = (gm < N_NODES) ? 16 : 0;                                  \
            if (gm >= N_NODES) gm = N_NODES - 1;                               \
            uint32_t dst = sbase + (STG) * A_STG_B + row * (A_LD * 4) + c4 * 16;\
            const char* src = (const char*)X + (size_t)gm * (IN_DIM * 4)       \
                              + (K0) * 4 + c4 * 16;                            \
            asm volatile("cp.async.cg.shared.global [%0], [%1], 16, %2;"       \
                         :: "r"(dst), "l"(src), "r"(sz));                      \
        }                                                                      \
        _Pragma("unroll")                                                      \
        for (int l = 0; l < 4; l++) {                                          \
            int idx = tid + l * 256;                                           \
            int kr = idx >> 5, c4 = idx & 31;                                  \
            uint32_t dst = sbase + B_BASE_B + (STG) * B_STG_B                  \
                           + kr * (B_LD * 4) + c4 * 16;                        \
            const char* src = (const char*)Wm                                  \
                + ((size_t)((K0) + kr) * OUT_DIM + n0) * 4 + c4 * 16;          \
            asm volatile("cp.async.cg.shared.global [%0], [%1], 16;"           \
                         :: "r"(dst), "l"(src));                               \
        }                                                                      \
        asm volatile("cp.async.commit_group;" ::: "memory");                   \
    } while (0)

    float c[4][4][4];
#pragma unroll
    for (int i = 0; i < 4; i++)
#pragma unroll
        for (int j = 0; j < 4; j++)
#pragma unroll
            for (int r = 0; r < 4; r++) c[i][j][r] = 0.f;

    ISSUE_STAGE(0, 0);
    ISSUE_STAGE(GBK, 1);

    for (int it = 0; it < NK_IT; it++) {
        if (it == NK_IT - 1) asm volatile("cp.async.wait_group 0;" ::: "memory");
        else                 asm volatile("cp.async.wait_group 1;" ::: "memory");
        __syncthreads();

        const int stg = it % 3;
        const float* Af = Asf + stg * (GBM * A_LD);
        const float* Bf = Bsf + stg * (GBK * B_LD);

#pragma unroll
        for (int ks = 0; ks < 4; ks++) {
            const int kb = ks * 8;
            uint32_t a[4][4], b[4][2];
#pragma unroll
            for (int mt = 0; mt < 4; mt++) {
                int rb = wm + mt * 16;
                a[mt][0] = f2tf32(Af[(rb + gID    ) * A_LD + kb + tig    ]);
                a[mt][1] = f2tf32(Af[(rb + gID + 8) * A_LD + kb + tig    ]);
                a[mt][2] = f2tf32(Af[(rb + gID    ) * A_LD + kb + tig + 4]);
                a[mt][3] = f2tf32(Af[(rb + gID + 8) * A_LD + kb + tig + 4]);
            }
#pragma unroll
            for (int nt = 0; nt < 4; nt++) {
                int col = wn + nt * 8 + gID;
                b[nt][0] = f2tf32(Bf[(kb + tig    ) * B_LD + col]);
                b[nt][1] = f2tf32(Bf[(kb + tig + 4) * B_LD + col]);
            }
#pragma unroll
            for (int mt = 0; mt < 4; mt++)
#pragma unroll
                for (int nt = 0; nt < 4; nt++) {
                    asm volatile(
                        "mma.sync.aligned.m16n8k8.row.col.f32.tf32.tf32.f32 "
                        "{%0,%1,%2,%3}, {%4,%5,%6,%7}, {%8,%9}, {%0,%1,%2,%3};"
                        : "+f"(c[mt][nt][0]), "+f"(c[mt][nt][1]),
                          "+f"(c[mt][nt][2]), "+f"(c[mt][nt][3])
                        : "r"(a[mt][0]), "r"(a[mt][1]), "r"(a[mt][2]), "r"(a[mt][3]),
                          "r"(b[nt][0]), "r"(b[nt][1]));
                }
        }

        if (it + 2 < NK_IT) {
            ISSUE_STAGE((it + 2) * GBK, (it + 2) % 3);
        }
    }
#undef ISSUE_STAGE

    // ---- epilogue 1: fp16 xp stores ----
#pragma unroll
    for (int mt = 0; mt < 4; mt++) {
        int r0 = m0 + wm + mt * 16 + gID;
#pragma unroll
        for (int nt = 0; nt < 4; nt++) {
            int col = n0 + wn + nt * 8 + 2 * tig;
            if (r0 < N_NODES) {
                __half2 v01 = __floats2half2_rn(c[mt][nt][0], c[mt][nt][1]);
                *reinterpret_cast<__half2*>(g_xph + (size_t)r0 * OUT_DIM + col) = v01;
            }
            if (r0 + 8 < N_NODES) {
                __half2 v23 = __floats2half2_rn(c[mt][nt][2], c[mt][nt][3]);
                *reinterpret_cast<__half2*>(g_xph + (size_t)(r0 + 8) * OUT_DIM + col) = v23;
            }
        }
    }

    // ---- epilogue 2: fused attention logits ----
    float psrc0[4], psrc1[4], pdst0[4], pdst1[4];
#pragma unroll
    for (int mt = 0; mt < 4; mt++) {
        psrc0[mt] = psrc1[mt] = pdst0[mt] = pdst1[mt] = 0.f;
#pragma unroll
        for (int nt = 0; nt < 4; nt++) {
            int col = n0 + wn + nt * 8 + 2 * tig;
            float as0 = att_src[col], as1 = att_src[col + 1];
            float ad0 = att_dst[col], ad1 = att_dst[col + 1];
            psrc0[mt] += c[mt][nt][0] * as0 + c[mt][nt][1] * as1;
            psrc1[mt] += c[mt][nt][2] * as0 + c[mt][nt][3] * as1;
            pdst0[mt] += c[mt][nt][0] * ad0 + c[mt][nt][1] * ad1;
            pdst1[mt] += c[mt][nt][2] * ad0 + c[mt][nt][3] * ad1;
        }
    }
#pragma unroll
    for (int off = 1; off <= 2; off <<= 1) {
#pragma unroll
        for (int mt = 0; mt < 4; mt++) {
            psrc0[mt] += __shfl_xor_sync(0xffffffffu, psrc0[mt], off);
            psrc1[mt] += __shfl_xor_sync(0xffffffffu, psrc1[mt], off);
            pdst0[mt] += __shfl_xor_sync(0xffffffffu, pdst0[mt], off);
            pdst1[mt] += __shfl_xor_sync(0xffffffffu, pdst1[mt], off);
        }
    }
    if (tig == 0) {
        int h = (n0 + wn) >> 6;
#pragma unroll
        for (int mt = 0; mt < 4; mt++) {
            int r0 = m0 + wm + mt * 16 + gID;
            if (r0 < N_NODES) {
                atomicAdd(&g_asrc[r0 * 4 + h], psrc0[mt]);
                atomicAdd(&g_adst[r0 * 4 + h], pdst0[mt]);
            }
            if (r0 + 8 < N_NODES) {
                atomicAdd(&g_asrc[(r0 + 8) * 4 + h], psrc1[mt]);
                atomicAdd(&g_adst[(r0 + 8) * 4 + h], pdst1[mt]);
            }
        }
    }
}

// ---------------- K3a: in-degree histogram ---------------------------------
__global__ __launch_bounds__(256) void hist_kernel(const void* __restrict__ ei)
{
    int i = blockIdx.x * blockDim.x + threadIdx.x;
    if (i >= E_TOT) return;
    int s, d;
    if (i < N_EDGES) load_edge(ei, i, s, d);
    else             d = i - N_EDGES;
    atomicAdd(&g_deg[d], 1);
}

// ---------------- K3b: fused exclusive scan (last-block-done pattern) ------
__global__ __launch_bounds__(256) void scan_fused_kernel()
{
    __shared__ int sm[256];
    __shared__ bool isLast;
    int tid = threadIdx.x;
    int i = blockIdx.x * 256 + tid;
    int v = (i < N_NODES) ? g_deg[i] : 0;
    sm[tid] = v;
    __syncthreads();
#pragma unroll
    for (int off = 1; off < 256; off <<= 1) {
        int t = (tid >= off) ? sm[tid - off] : 0;
        __syncthreads();
        sm[tid] += t;
        __syncthreads();
    }
    int incl = sm[tid];
    if (i < N_NODES) {
        int excl = incl - v;
        g_off[i] = excl;
        g_cur[i] = excl;
    }
    if (tid == 255) g_bsum[blockIdx.x] = incl;

    __threadfence();
    if (tid == 0) {
        int ticket = atomicAdd(&g_scan_ctr, 1);
        isLast = (ticket == gridDim.x - 1);
    }
    __syncthreads();
    if (isLast) {
        int bv = (tid < NBLK_SCAN) ? g_bsum[tid] : 0;
        sm[tid] = bv;
        __syncthreads();
#pragma unroll
        for (int off = 1; off < 256; off <<= 1) {
            int t = (tid >= off) ? sm[tid - off] : 0;
            __syncthreads();
            sm[tid] += t;
            __syncthreads();
        }
        if (tid < NBLK_SCAN) g_boff[tid] = sm[tid] - bv;
    }
}

// ---------------- K3c: scatter edges into CSR order + compute exp(logit) ---
__global__ __launch_bounds__(256) void scatter_kernel(const void* __restrict__ ei)
{
    int i = blockIdx.x * blockDim.x + threadIdx.x;
    if (i >= E_TOT) return;
    int s, d;
    if (i < N_EDGES) load_edge(ei, i, s, d);
    else             s = d = i - N_EDGES;   // self-loop

    float4 as = *reinterpret_cast<const float4*>(g_asrc + s * 4);
    float4 ad = *reinterpret_cast<const float4*>(g_adst + d * 4);
    float e0 = as.x + ad.x, e1 = as.y + ad.y, e2 = as.z + ad.z, e3 = as.w + ad.w;
    e0 = (e0 > 0.f) ? e0 : NEG_SLOPE * e0;
    e1 = (e1 > 0.f) ? e1 : NEG_SLOPE * e1;
    e2 = (e2 > 0.f) ? e2 : NEG_SLOPE * e2;
    e3 = (e3 > 0.f) ? e3 : NEG_SLOPE * e3;
    float4 ee = make_float4(__expf(e0), __expf(e1), __expf(e2), __expf(e3));

    int pos = atomicAdd(&g_cur[d], 1) + g_boff[d >> 8];
    g_csr_src[pos] = s;
    *reinterpret_cast<float4*>(g_csr_ee + (size_t)pos * 4) = ee;
}

// ---------------- K4: CSR aggregate (simple loop), fused softmax + ReLU ----
__global__ __launch_bounds__(256) void aggregate_csr_kernel(float* __restrict__ out)
{
    int d = (blockIdx.x * blockDim.x + threadIdx.x) >> 5;
    if (d >= N_NODES) return;
    int lane = threadIdx.x & 31;
    int h = lane >> 3;
    int boff = g_boff[d >> 8];
    int beg = g_off[d] + boff;
    int end = g_cur[d] + boff;

    float a0 = 0.f, a1 = 0.f, a2 = 0.f, a3 = 0.f;
    float a4 = 0.f, a5 = 0.f, a6 = 0.f, a7 = 0.f;
    float denom = 0.f;

    for (int j = beg; j < end; j++) {
        int   s  = __ldg(g_csr_src + j);
        float ee = __ldg(g_csr_ee + (size_t)j * 4 + h);
        denom += ee;
        uint4 u = __ldg(reinterpret_cast<const uint4*>(
            g_xph + (size_t)s * OUT_DIM + lane * 8));
        const __half2* hp = reinterpret_cast<const __half2*>(&u);
        float2 f0 = __half22float2(hp[0]);
        float2 f1 = __half22float2(hp[1]);
        float2 f2 = __half22float2(hp[2]);
        float2 f3 = __half22float2(hp[3]);
        a0 += ee * f0.x; a1 += ee * f0.y;
        a2 += ee * f1.x; a3 += ee * f1.y;
        a4 += ee * f2.x; a5 += ee * f2.y;
        a6 += ee * f3.x; a7 += ee * f3.y;
    }

    float inv = 1.f / denom;
    float4 o0 = make_float4(fmaxf(a0 * inv, 0.f), fmaxf(a1 * inv, 0.f),
                            fmaxf(a2 * inv, 0.f), fmaxf(a3 * inv, 0.f));
    float4 o1 = make_float4(fmaxf(a4 * inv, 0.f), fmaxf(a5 * inv, 0.f),
                            fmaxf(a6 * inv, 0.f), fmaxf(a7 * inv, 0.f));
    float4* op = reinterpret_cast<float4*>(out + (size_t)d * OUT_DIM + lane * 8);
    __stcs(op, o0);
    __stcs(op + 1, o1);
}

// ---------------- launch ----------------------------------------------------
extern "C" void kernel_launch(void* const* d_in, const int* in_sizes, int n_in,
                              void* d_out, int out_size)
{
    const float* x       = (const float*)d_in[0];
    const void*  ei      = d_in[1];
    const float* Wm      = (const float*)d_in[2];
    const float* att_src = (const float*)d_in[3];
    const float* att_dst = (const float*)d_in[4];
    float*       out     = (float*)d_out;

    static cudaStream_t s1 = nullptr;
    static cudaEvent_t evFork = nullptr, evJoin = nullptr;
    if (!s1) {
        cudaStreamCreateWithFlags(&s1, cudaStreamNonBlocking);
        cudaEventCreateWithFlags(&evFork, cudaEventDisableTiming);
        cudaEventCreateWithFlags(&evJoin, cudaEventDisableTiming);
        cudaFuncSetAttribute(gemm_tf32_kernel,
                             cudaFuncAttributeMaxDynamicSharedMemorySize, GEMM_SMEM);
    }

    cudaEventRecord(evFork, 0);
    cudaStreamWaitEvent(s1, evFork, 0);

    // branch B (side stream): deg-zero -> hist -> fused scan
    zero_deg_kernel<<<NBLK_SCAN, 256, 0, s1>>>();
    hist_kernel<<<(E_TOT + 255) / 256, 256, 0, s1>>>(ei);
    scan_fused_kernel<<<NBLK_SCAN, 256, 0, s1>>>();
    cudaEventRecord(evJoin, s1);

    // branch A (main stream): logit-zero -> GEMM + fused logits
    zero_logit_kernel<<<NBLK_SCAN, 256>>>((const int*)ei);
    dim3 ggrid((N_NODES + GBM - 1) / GBM, OUT_DIM / GBN);
    gemm_tf32_kernel<<<ggrid, 256, GEMM_SMEM>>>(x, Wm, att_src, att_dst);

    // join: scatter needs logits (A) + cursors (B)
    cudaStreamWaitEvent(0, evJoin, 0);
    scatter_kernel<<<(E_TOT + 255) / 256, 256>>>(ei);

    aggregate_csr_kernel<<<((size_t)N_NODES * 32 + 255) / 256, 256>>>(out);
}

// round 14
// speedup vs baseline: 2.6417x; 1.0767x over previous
#include <cuda_runtime.h>
#include <cuda_fp16.h>
#include <cstdint>

#define N_NODES 50000
#define N_EDGES 800000
#define E_TOT   (N_EDGES + N_NODES)
#define IN_DIM  256
#define OUT_DIM 256   // N_HEADS * HEAD_DIM
#define NEG_SLOPE 0.2f
#define NBLK_SCAN ((N_NODES + 255) / 256)   // 196

// ---------------- scratch (static device globals; no runtime allocation) ---
__device__ __align__(16) __half g_xph[(size_t)N_NODES * OUT_DIM]; // projected features, fp16 [N,256]
__device__ __align__(16) float g_asrc[N_NODES * 4];               // per-node src logits [N,4]
__device__ __align__(16) float g_adst[N_NODES * 4];               // per-node dst logits [N,4]
__device__ int g_csr_src[E_TOT];                                  // src node id, CSR order
__device__ int g_deg[N_NODES];                                    // in-degree histogram
__device__ int g_off[N_NODES];                                    // CSR row start (block-LOCAL exclusive)
__device__ int g_cur[N_NODES];                                    // scatter cursor (block-LOCAL)
__device__ int g_bsum[NBLK_SCAN];                                 // per-block degree sums
__device__ int g_boff[NBLK_SCAN];                                 // scanned block offsets
__device__ int g_scan_ctr;                                        // last-block ticket
__device__ int g_is64;                                            // edge_index dtype flag

// ---------------- helpers --------------------------------------------------
__device__ __forceinline__ uint32_t f2tf32(float f) {
    uint32_t r;
    asm("cvt.rna.tf32.f32 %0, %1;" : "=r"(r) : "f"(f));
    return r;
}

__device__ __forceinline__ void load_edge(const void* ei, int i, int& s, int& d) {
    if (g_is64) {
        const long long* p = (const long long*)ei;
        s = (int)p[i];
        d = (int)p[N_EDGES + i];
    } else {
        const int* p = (const int*)ei;
        s = p[i];
        d = p[N_EDGES + i];
    }
}

// ---------------- K0: zero degrees + ticket + dtype detect (side stream) ---
// Detection lives HERE (same stream as hist/scatter, its only consumers).
__global__ void zero_deg_kernel(const int* __restrict__ ei32) {
    __shared__ int s_any[128];
    int i = blockIdx.x * blockDim.x + threadIdx.x;
    if (i < N_NODES) g_deg[i] = 0;
    if (blockIdx.x == 0) {
        int t = threadIdx.x;
        if (t == 0) g_scan_ctr = 0;
        if (t < 128) s_any[t] = ei32[2 * t + 1];   // parallel probe of odd words
        __syncthreads();
        if (t < 64) s_any[t] |= s_any[t + 64];
        __syncthreads();
        if (t < 32) {
            int v = s_any[t] | s_any[t + 32];
#pragma unroll
            for (int off = 16; off > 0; off >>= 1)
                v |= __shfl_down_sync(0xffffffffu, v, off);
            if (t == 0) g_is64 = (v == 0) ? 1 : 0;
        }
    }
}

// ---------------- K1: GEMM xp = x @ W (tf32 mma, cp.async 3-stage, ---------
//                      fused atomic-free logit epilogue, 2 CTAs/SM)
#define GBM 128
#define GBN 128
#define GBK 32
#define NK_IT (IN_DIM / GBK)      // 8
#define A_LD 36
#define B_LD 136
#define A_STG_B (GBM * A_LD * 4)
#define B_STG_B (GBK * B_LD * 4)
#define B_BASE_B (3 * A_STG_B)
#define GEMM_SMEM (3 * (A_STG_B + B_STG_B))  // 107520

__global__ __launch_bounds__(256, 2) void gemm_tf32_kernel(
    const float* __restrict__ X, const float* __restrict__ Wm,
    const float* __restrict__ att_src, const float* __restrict__ att_dst)
{
    extern __shared__ char smem_raw[];
    float* Asf = reinterpret_cast<float*>(smem_raw);
    float* Bsf = reinterpret_cast<float*>(smem_raw + B_BASE_B);
    const uint32_t sbase = (uint32_t)__cvta_generic_to_shared(smem_raw);

    const int tid  = threadIdx.x;
    const int wid  = tid >> 5;
    const int lane = tid & 31;
    const int m0 = blockIdx.x * GBM;
    const int n0 = blockIdx.y * GBN;
    const int wm = (wid & 1) * 64;
    const int wn = (wid >> 1) * 32;
    const int gID = lane >> 2;
    const int tig = lane & 3;

#define ISSUE_STAGE(K0, STG) do {                                              \
        _Pragma("unroll")                                                      \
        for (int l = 0; l < 4; l++) {                                          \
            int idx = tid + l * 256;                                           \
            int row = idx >> 3, c4 = idx & 7;                                  \
            int gm = m0 + row;                                                 \
            int sz = (gm < N_NODES) ? 16 : 0;                                  \
            if (gm >= N_NODES) gm = N_NODES - 1;                               \
            uint32_t dst = sbase + (STG) * A_STG_B + row * (A_LD * 4) + c4 * 16;\
            const char* src = (const char*)X + (size_t)gm * (IN_DIM * 4)       \
                              + (K0) * 4 + c4 * 16;                            \
            asm volatile("cp.async.cg.shared.global [%0], [%1], 16, %2;"       \
                         :: "r"(dst), "l"(src), "r"(sz));                      \
        }                                                                      \
        _Pragma("unroll")                                                      \
        for (int l = 0; l < 4; l++) {                                          \
            int idx = tid + l * 256;                                           \
            int kr = idx >> 5, c4 = idx & 31;                                  \
            uint32_t dst = sbase + B_BASE_B + (STG) * B_STG_B                  \
                           + kr * (B_LD * 4) + c4 * 16;                        \
            const char* src = (const char*)Wm                                  \
                + ((size_t)((K0) + kr) * OUT_DIM + n0) * 4 + c4 * 16;          \
            asm volatile("cp.async.cg.shared.global [%0], [%1], 16;"           \
                         :: "r"(dst), "l"(src));                               \
        }                                                                      \
        asm volatile("cp.async.commit_group;" ::: "memory");                   \
    } while (0)

    float c[4][4][4];
#pragma unroll
    for (int i = 0; i < 4; i++)
#pragma unroll
        for (int j = 0; j < 4; j++)
#pragma unroll
            for (int r = 0; r < 4; r++) c[i][j][r] = 0.f;

    ISSUE_STAGE(0, 0);
    ISSUE_STAGE(GBK, 1);

    for (int it = 0; it < NK_IT; it++) {
        if (it == NK_IT - 1) asm volatile("cp.async.wait_group 0;" ::: "memory");
        else                 asm volatile("cp.async.wait_group 1;" ::: "memory");
        __syncthreads();

        const int stg = it % 3;
        const float* Af = Asf + stg * (GBM * A_LD);
        const float* Bf = Bsf + stg * (GBK * B_LD);

#pragma unroll
        for (int ks = 0; ks < 4; ks++) {
            const int kb = ks * 8;
            uint32_t a[4][4], b[4][2];
#pragma unroll
            for (int mt = 0; mt < 4; mt++) {
                int rb = wm + mt * 16;
                a[mt][0] = f2tf32(Af[(rb + gID    ) * A_LD + kb + tig    ]);
                a[mt][1] = f2tf32(Af[(rb + gID + 8) * A_LD + kb + tig    ]);
                a[mt][2] = f2tf32(Af[(rb + gID    ) * A_LD + kb + tig + 4]);
                a[mt][3] = f2tf32(Af[(rb + gID + 8) * A_LD + kb + tig + 4]);
            }
#pragma unroll
            for (int nt = 0; nt < 4; nt++) {
                int col = wn + nt * 8 + gID;
                b[nt][0] = f2tf32(Bf[(kb + tig    ) * B_LD + col]);
                b[nt][1] = f2tf32(Bf[(kb + tig + 4) * B_LD + col]);
            }
#pragma unroll
            for (int mt = 0; mt < 4; mt++)
#pragma unroll
                for (int nt = 0; nt < 4; nt++) {
                    asm volatile(
                        "mma.sync.aligned.m16n8k8.row.col.f32.tf32.tf32.f32 "
                        "{%0,%1,%2,%3}, {%4,%5,%6,%7}, {%8,%9}, {%0,%1,%2,%3};"
                        : "+f"(c[mt][nt][0]), "+f"(c[mt][nt][1]),
                          "+f"(c[mt][nt][2]), "+f"(c[mt][nt][3])
                        : "r"(a[mt][0]), "r"(a[mt][1]), "r"(a[mt][2]), "r"(a[mt][3]),
                          "r"(b[nt][0]), "r"(b[nt][1]));
                }
        }

        if (it + 2 < NK_IT) {
            ISSUE_STAGE((it + 2) * GBK, (it + 2) % 3);
        }
    }
#undef ISSUE_STAGE

    // ---- epilogue 1: fp16 xp stores ----
#pragma unroll
    for (int mt = 0; mt < 4; mt++) {
        int r0 = m0 + wm + mt * 16 + gID;
#pragma unroll
        for (int nt = 0; nt < 4; nt++) {
            int col = n0 + wn + nt * 8 + 2 * tig;
            if (r0 < N_NODES) {
                __half2 v01 = __floats2half2_rn(c[mt][nt][0], c[mt][nt][1]);
                *reinterpret_cast<__half2*>(g_xph + (size_t)r0 * OUT_DIM + col) = v01;
            }
            if (r0 + 8 < N_NODES) {
                __half2 v23 = __floats2half2_rn(c[mt][nt][2], c[mt][nt][3]);
                *reinterpret_cast<__half2*>(g_xph + (size_t)(r0 + 8) * OUT_DIM + col) = v23;
            }
        }
    }

    // ---- epilogue 2: attention logits, atomic-free -------------------------
    // Per (row, head) exactly two warps contribute: (wm, wn) and (wm, wn+32).
    // Quad-reduce within warp, pair-combine via (reused) smem, direct store.
    float psrc0[4], psrc1[4], pdst0[4], pdst1[4];
#pragma unroll
    for (int mt = 0; mt < 4; mt++) {
        psrc0[mt] = psrc1[mt] = pdst0[mt] = pdst1[mt] = 0.f;
#pragma unroll
        for (int nt = 0; nt < 4; nt++) {
            int col = n0 + wn + nt * 8 + 2 * tig;
            float as0 = att_src[col], as1 = att_src[col + 1];
            float ad0 = att_dst[col], ad1 = att_dst[col + 1];
            psrc0[mt] += c[mt][nt][0] * as0 + c[mt][nt][1] * as1;
            psrc1[mt] += c[mt][nt][2] * as0 + c[mt][nt][3] * as1;
            pdst0[mt] += c[mt][nt][0] * ad0 + c[mt][nt][1] * ad1;
            pdst1[mt] += c[mt][nt][2] * ad0 + c[mt][nt][3] * ad1;
        }
    }
#pragma unroll
    for (int off = 1; off <= 2; off <<= 1) {
#pragma unroll
        for (int mt = 0; mt < 4; mt++) {
            psrc0[mt] += __shfl_xor_sync(0xffffffffu, psrc0[mt], off);
            psrc1[mt] += __shfl_xor_sync(0xffffffffu, psrc1[mt], off);
            pdst0[mt] += __shfl_xor_sync(0xffffffffu, pdst0[mt], off);
            pdst1[mt] += __shfl_xor_sync(0xffffffffu, pdst1[mt], off);
        }
    }
    // stash partials in smem (pipeline done with it)
    float* red = reinterpret_cast<float*>(smem_raw);   // [8][4][4][8] floats
    __syncthreads();
    if (tig == 0) {
#pragma unroll
        for (int mt = 0; mt < 4; mt++) {
            int base = wid * 128 + mt * 32 + gID;
            red[base +  0] = psrc0[mt];
            red[base +  8] = psrc1[mt];
            red[base + 16] = pdst0[mt];
            red[base + 24] = pdst1[mt];
        }
    }
    __syncthreads();
    if ((((wid >> 1) & 1) == 0) && tig == 0) {
        int pw = wid + 2;                       // partner warp (wn + 32)
        int h = (n0 + wn) >> 6;                 // global head 0..3
#pragma unroll
        for (int mt = 0; mt < 4; mt++) {
            int pb = pw * 128 + mt * 32 + gID;
            float s0 = psrc0[mt] + red[pb +  0];
            float s1 = psrc1[mt] + red[pb +  8];
            float d0 = pdst0[mt] + red[pb + 16];
            float d1 = pdst1[mt] + red[pb + 24];
            int r0 = m0 + wm + mt * 16 + gID;
            if (r0 < N_NODES) {
                g_asrc[r0 * 4 + h] = s0;
                g_adst[r0 * 4 + h] = d0;
            }
            if (r0 + 8 < N_NODES) {
                g_asrc[(r0 + 8) * 4 + h] = s1;
                g_adst[(r0 + 8) * 4 + h] = d1;
            }
        }
    }
}

// ---------------- K3a: in-degree histogram ---------------------------------
__global__ __launch_bounds__(256) void hist_kernel(const void* __restrict__ ei)
{
    int i = blockIdx.x * blockDim.x + threadIdx.x;
    if (i >= E_TOT) return;
    int s, d;
    if (i < N_EDGES) load_edge(ei, i, s, d);
    else             d = i - N_EDGES;
    atomicAdd(&g_deg[d], 1);
}

// ---------------- K3b: fused exclusive scan (last-block-done pattern) ------
__global__ __launch_bounds__(256) void scan_fused_kernel()
{
    __shared__ int sm[256];
    __shared__ bool isLast;
    int tid = threadIdx.x;
    int i = blockIdx.x * 256 + tid;
    int v = (i < N_NODES) ? g_deg[i] : 0;
    sm[tid] = v;
    __syncthreads();
#pragma unroll
    for (int off = 1; off < 256; off <<= 1) {
        int t = (tid >= off) ? sm[tid - off] : 0;
        __syncthreads();
        sm[tid] += t;
        __syncthreads();
    }
    int incl = sm[tid];
    if (i < N_NODES) {
        int excl = incl - v;
        g_off[i] = excl;
        g_cur[i] = excl;
    }
    if (tid == 255) g_bsum[blockIdx.x] = incl;

    __threadfence();
    if (tid == 0) {
        int ticket = atomicAdd(&g_scan_ctr, 1);
        isLast = (ticket == gridDim.x - 1);
    }
    __syncthreads();
    if (isLast) {
        int bv = (tid < NBLK_SCAN) ? g_bsum[tid] : 0;
        sm[tid] = bv;
        __syncthreads();
#pragma unroll
        for (int off = 1; off < 256; off <<= 1) {
            int t = (tid >= off) ? sm[tid - off] : 0;
            __syncthreads();
            sm[tid] += t;
            __syncthreads();
        }
        if (tid < NBLK_SCAN) g_boff[tid] = sm[tid] - bv;
    }
}

// ---------------- K3c: scatter edges into CSR order (index only) -----------
// No logit dependency -> runs on the side stream, overlapped with the GEMM.
__global__ __launch_bounds__(256) void scatter_kernel(const void* __restrict__ ei)
{
    int i = blockIdx.x * blockDim.x + threadIdx.x;
    if (i >= E_TOT) return;
    int s, d;
    if (i < N_EDGES) load_edge(ei, i, s, d);
    else             s = d = i - N_EDGES;   // self-loop

    int pos = atomicAdd(&g_cur[d], 1) + g_boff[d >> 8];
    g_csr_src[pos] = s;
}

// ---------------- K4: CSR aggregate with inline softmax + ReLU -------------
// ee computed in-loop from logits (exact same formula as before).
__global__ __launch_bounds__(256) void aggregate_csr_kernel(float* __restrict__ out)
{
    int d = (blockIdx.x * blockDim.x + threadIdx.x) >> 5;
    if (d >= N_NODES) return;
    int lane = threadIdx.x & 31;
    int h = lane >> 3;
    int boff = g_boff[d >> 8];
    int beg = g_off[d] + boff;
    int end = g_cur[d] + boff;
    float adh = __ldg(g_adst + d * 4 + h);   // invariant over the row

    float a0 = 0.f, a1 = 0.f, a2 = 0.f, a3 = 0.f;
    float a4 = 0.f, a5 = 0.f, a6 = 0.f, a7 = 0.f;
    float denom = 0.f;

    for (int j = beg; j < end; j++) {
        int   s  = __ldg(g_csr_src + j);
        float e  = __ldg(g_asrc + s * 4 + h) + adh;
        e = (e > 0.f) ? e : NEG_SLOPE * e;
        float ee = __expf(e);
        denom += ee;
        uint4 u = __ldg(reinterpret_cast<const uint4*>(
            g_xph + (size_t)s * OUT_DIM + lane * 8));
        const __half2* hp = reinterpret_cast<const __half2*>(&u);
        float2 f0 = __half22float2(hp[0]);
        float2 f1 = __half22float2(hp[1]);
        float2 f2 = __half22float2(hp[2]);
        float2 f3 = __half22float2(hp[3]);
        a0 += ee * f0.x; a1 += ee * f0.y;
        a2 += ee * f1.x; a3 += ee * f1.y;
        a4 += ee * f2.x; a5 += ee * f2.y;
        a6 += ee * f3.x; a7 += ee * f3.y;
    }

    float inv = 1.f / denom;
    float4 o0 = make_float4(fmaxf(a0 * inv, 0.f), fmaxf(a1 * inv, 0.f),
                            fmaxf(a2 * inv, 0.f), fmaxf(a3 * inv, 0.f));
    float4 o1 = make_float4(fmaxf(a4 * inv, 0.f), fmaxf(a5 * inv, 0.f),
                            fmaxf(a6 * inv, 0.f), fmaxf(a7 * inv, 0.f));
    float4* op = reinterpret_cast<float4*>(out + (size_t)d * OUT_DIM + lane * 8);
    __stcs(op, o0);
    __stcs(op + 1, o1);
}

// ---------------- launch ----------------------------------------------------
extern "C" void kernel_launch(void* const* d_in, const int* in_sizes, int n_in,
                              void* d_out, int out_size)
{
    const float* x       = (const float*)d_in[0];
    const void*  ei      = d_in[1];
    const float* Wm      = (const float*)d_in[2];
    const float* att_src = (const float*)d_in[3];
    const float* att_dst = (const float*)d_in[4];
    float*       out     = (float*)d_out;

    static cudaStream_t s1 = nullptr;
    static cudaEvent_t evFork = nullptr, evJoin = nullptr;
    if (!s1) {
        cudaStreamCreateWithFlags(&s1, cudaStreamNonBlocking);
        cudaEventCreateWithFlags(&evFork, cudaEventDisableTiming);
        cudaEventCreateWithFlags(&evJoin, cudaEventDisableTiming);
        cudaFuncSetAttribute(gemm_tf32_kernel,
                             cudaFuncAttributeMaxDynamicSharedMemorySize, GEMM_SMEM);
    }

    cudaEventRecord(evFork, 0);
    cudaStreamWaitEvent(s1, evFork, 0);

    // branch B (side stream): deg-zero+detect -> hist -> scan -> scatter
    zero_deg_kernel<<<NBLK_SCAN, 256, 0, s1>>>((const int*)ei);
    hist_kernel<<<(E_TOT + 255) / 256, 256, 0, s1>>>(ei);
    scan_fused_kernel<<<NBLK_SCAN, 256, 0, s1>>>();
    scatter_kernel<<<(E_TOT + 255) / 256, 256, 0, s1>>>(ei);
    cudaEventRecord(evJoin, s1);

    // branch A (main stream): GEMM + atomic-free logit epilogue
    dim3 ggrid((N_NODES + GBM - 1) / GBM, OUT_DIM / GBN);
    gemm_tf32_kernel<<<ggrid, 256, GEMM_SMEM>>>(x, Wm, att_src, att_dst);

    // join: aggregate needs logits+xp (A) and CSR (B)
    cudaStreamWaitEvent(0, evJoin, 0);
    aggregate_csr_kernel<<<((size_t)N_NODES * 32 + 255) / 256, 256>>>(out);
}